// round 2
// baseline (speedup 1.0000x reference)
#include <cuda_runtime.h>
#include <math.h>

// Problem constants
#define BB  64
#define SS  512
#define HH  768
#define NN  128
#define EE  1024
#define GHD 128
#define FHD 256
#define LL  2
#define BNN (BB*NN)   // 8192

// ---------------- scratch (device globals; no allocation allowed) ----------------
__device__ float g_gate[BB*SS];       // 32768
__device__ float g_cnt[BNN];          // 8192
__device__ float g_nf[(size_t)BNN*HH];// 25 MB
__device__ float g_dinv[BNN];
__device__ float g_x1[(size_t)BNN*GHD];
__device__ float g_h1[(size_t)BNN*GHD];
__device__ float g_x2[(size_t)BNN*GHD];
__device__ float g_pool[BB*GHD];

// ---------------- K0: zero counts ----------------
__global__ void k_zero() {
    int i = blockIdx.x*blockDim.x + threadIdx.x;
    if (i < BNN) g_cnt[i] = 0.f;
}

// ---------------- K1: gate = sigmoid(lh . wr + br); counts ----------------
__global__ void k_gate(const float* __restrict__ lh, const int* __restrict__ submap,
                       const float* __restrict__ wr, const float* __restrict__ brp) {
    int warp = (blockIdx.x*blockDim.x + threadIdx.x) >> 5;
    int lane = threadIdx.x & 31;
    if (warp >= BB*SS) return;
    const float4* row4 = (const float4*)(lh + (size_t)warp*HH);
    const float4* w4   = (const float4*)wr;
    float dot = 0.f;
    #pragma unroll
    for (int i = 0; i < 6; i++) {
        float4 a = row4[lane + 32*i];
        float4 w = w4[lane + 32*i];
        dot += a.x*w.x + a.y*w.y + a.z*w.z + a.w*w.w;
    }
    #pragma unroll
    for (int off = 16; off; off >>= 1) dot += __shfl_xor_sync(0xffffffffu, dot, off);
    if (lane == 0) {
        float g = 1.f/(1.f + expf(-(dot + brp[0])));
        g_gate[warp] = g;
        int b = warp / SS;
        atomicAdd(&g_cnt[b*NN + submap[warp]], 1.f);
    }
}

// ---------------- K2: segment mean of gated features, per (batch, 256-dim chunk) ----
__global__ void k_segsum(const float* __restrict__ lh, const int* __restrict__ submap) {
    extern __shared__ float sm[];
    float* acc    = sm;                  // NN*256
    float* gate_s = sm + NN*256;         // SS
    int*   sub_s  = (int*)(gate_s + SS); // SS
    int b   = blockIdx.y;
    int c0  = blockIdx.x*256;
    int tid = threadIdx.x;               // 256 threads
    for (int i = tid; i < NN*256; i += 256) acc[i] = 0.f;
    for (int s = tid; s < SS; s += 256) {
        gate_s[s] = g_gate[b*SS + s];
        sub_s[s]  = submap[b*SS + s];
    }
    __syncthreads();
    const float* base = lh + ((size_t)b*SS)*HH + c0;
    for (int s0 = 0; s0 < SS; s0 += 4) {
        float v[4], g[4]; int n[4];
        #pragma unroll
        for (int j = 0; j < 4; j++) {
            v[j] = base[(size_t)(s0+j)*HH + tid];
            n[j] = sub_s[s0+j];
            g[j] = gate_s[s0+j];
        }
        #pragma unroll
        for (int j = 0; j < 4; j++)
            atomicAdd(&acc[n[j]*256 + tid], v[j]*g[j]);
    }
    __syncthreads();
    for (int n = 0; n < NN; n++) {
        float r = 1.f/fmaxf(g_cnt[b*NN + n], 1.f);
        g_nf[((size_t)(b*NN + n))*HH + c0 + tid] = acc[n*256 + tid]*r;
    }
}

// ---------------- K3: degree -> dinv (self-loop included) ----------------
__global__ void k_deg(const int* __restrict__ ei) {
    __shared__ float deg_s[NN];
    int b = blockIdx.x, tid = threadIdx.x; // 128 threads
    deg_s[tid] = 1.f; // self loop
    __syncthreads();
    const int* dst = ei + (size_t)b*2*EE + EE;
    for (int e = tid; e < EE; e += 128) atomicAdd(&deg_s[dst[e]], 1.f);
    __syncthreads();
    g_dinv[b*NN + tid] = rsqrtf(deg_s[tid]);
}

// ---------------- K4/K6: fp32 GEMM  C[BNN x 128] = A[BNN x K] @ W[K x 128] --------
__global__ void k_gemm(const float* __restrict__ A, const float* __restrict__ W,
                       float* __restrict__ C, int K) {
    __shared__ float As[16][68];   // padded
    __shared__ float Bs[16][128];
    int tid = threadIdx.x;               // 256
    int tx = tid & 15, ty = tid >> 4;
    int row0 = blockIdx.x*64;
    int a_row = tid >> 2;
    int a_c4  = (tid & 3)*4;
    int b_row = tid >> 5;                // 0..7
    int b_c4  = (tid & 31)*4;
    float acc[4][8];
    #pragma unroll
    for (int i = 0; i < 4; i++)
        #pragma unroll
        for (int j = 0; j < 8; j++) acc[i][j] = 0.f;

    for (int k0 = 0; k0 < K; k0 += 16) {
        float4 av = *(const float4*)&A[(size_t)(row0 + a_row)*K + k0 + a_c4];
        As[a_c4+0][a_row] = av.x; As[a_c4+1][a_row] = av.y;
        As[a_c4+2][a_row] = av.z; As[a_c4+3][a_row] = av.w;
        #pragma unroll
        for (int r = 0; r < 2; r++)
            *(float4*)&Bs[b_row + 8*r][b_c4] =
                *(const float4*)&W[(size_t)(k0 + b_row + 8*r)*128 + b_c4];
        __syncthreads();
        #pragma unroll
        for (int kk = 0; kk < 16; kk++) {
            float a0 = As[kk][ty*4+0], a1 = As[kk][ty*4+1];
            float a2 = As[kk][ty*4+2], a3 = As[kk][ty*4+3];
            float bb[8];
            #pragma unroll
            for (int j = 0; j < 8; j++) bb[j] = Bs[kk][tx + 16*j];
            #pragma unroll
            for (int j = 0; j < 8; j++) {
                acc[0][j] += a0*bb[j]; acc[1][j] += a1*bb[j];
                acc[2][j] += a2*bb[j]; acc[3][j] += a3*bb[j];
            }
        }
        __syncthreads();
    }
    #pragma unroll
    for (int i = 0; i < 4; i++) {
        float* cr = &C[(size_t)(row0 + ty*4 + i)*128];
        #pragma unroll
        for (int j = 0; j < 8; j++) cr[tx + 16*j] = acc[i][j];
    }
}

// ---------------- K5/K7: GCN message passing (one CTA per batch) ----------------
// out[dst] = relu( dinv[dst] * sum_{(src,dst)} (x[src]*dinv[src]) + bias )
// self loop handled by initializing accumulator with pre-scaled features.
template <bool POOL>
__global__ void k_msg(const float* __restrict__ X, const float* __restrict__ bias,
                      const int* __restrict__ ei, float* __restrict__ outp) {
    extern __shared__ float sm[];
    float* hp     = sm;                   // NN*GHD
    float* acc    = sm + NN*GHD;          // NN*GHD
    float* dinv_s = acc + NN*GHD;         // NN
    float* bias_s = dinv_s + NN;          // GHD
    int*   src_s  = (int*)(bias_s + GHD); // EE
    int*   dst_s  = src_s + EE;           // EE
    int b = blockIdx.x, tid = threadIdx.x; // 256 threads

    if (tid < NN)  dinv_s[tid] = g_dinv[b*NN + tid];
    if (tid < GHD) bias_s[tid] = bias[tid];
    for (int e = tid; e < EE; e += 256) {
        src_s[e] = ei[(size_t)b*2*EE + e];
        dst_s[e] = ei[(size_t)b*2*EE + EE + e];
    }
    __syncthreads();
    for (int i = tid; i < NN*GHD; i += 256) {
        int n = i >> 7;
        float v = X[(size_t)(b*NN)*GHD + i] * dinv_s[n];
        hp[i] = v; acc[i] = v;  // acc init = self-loop message
    }
    __syncthreads();
    int d = tid & 127;
    for (int e = tid >> 7; e < EE; e += 2)
        atomicAdd(&acc[dst_s[e]*GHD + d], hp[src_s[e]*GHD + d]);
    __syncthreads();
    for (int i = tid; i < NN*GHD; i += 256) {
        int n = i >> 7, dd = i & 127;
        float v = fmaxf(acc[i]*dinv_s[n] + bias_s[dd], 0.f);
        if (POOL) acc[i] = v;
        else      outp[(size_t)(b*NN)*GHD + i] = v;
    }
    if (POOL) {
        __syncthreads();
        if (tid < GHD) {
            float s = 0.f;
            for (int n = 0; n < NN; n++) s += acc[n*GHD + tid];
            outp[b*GHD + tid] = s * (1.f/NN);
        }
    }
}

// ---------------- K8: final 2-layer MLP ----------------
__global__ void k_fc(const float* __restrict__ lh, const float* __restrict__ Wf1,
                     const float* __restrict__ bf1, const float* __restrict__ Wf2,
                     const float* __restrict__ bf2, float* __restrict__ out) {
    __shared__ float in_s[HH + GHD]; // 896
    __shared__ float hs[FHD];        // 256
    int b = blockIdx.x, tid = threadIdx.x; // 256 threads
    for (int i = tid; i < HH; i += 256) in_s[i] = lh[(size_t)b*SS*HH + i];
    if (tid < GHD) in_s[HH + tid] = g_pool[b*GHD + tid];
    __syncthreads();
    float a = bf1[tid];
    #pragma unroll 4
    for (int k = 0; k < HH + GHD; k++) a += in_s[k]*Wf1[(size_t)k*FHD + tid];
    hs[tid] = fmaxf(a, 0.f);
    __syncthreads();
    if (tid < LL) {
        float o = bf2[tid];
        for (int j = 0; j < FHD; j++) o += hs[j]*Wf2[j*LL + tid];
        out[b*LL + tid] = o;
    }
}

// ---------------- launch ----------------
extern "C" void kernel_launch(void* const* d_in, const int* in_sizes, int n_in,
                              void* d_out, int out_size) {
    const float* lh     = (const float*)d_in[0];
    const int*   submap = (const int*)d_in[1];
    const int*   ei     = (const int*)d_in[2];
    // num_nodes may or may not be materialized as input 3 (size-1); be robust.
    int wbase = (in_sizes[3] == 1) ? 3 : 2;  // index just before wr
    const float* wr  = (const float*)d_in[wbase + 1];
    const float* br  = (const float*)d_in[wbase + 2];
    const float* W1  = (const float*)d_in[wbase + 3];
    const float* b1  = (const float*)d_in[wbase + 4];
    const float* W2  = (const float*)d_in[wbase + 5];
    const float* b2  = (const float*)d_in[wbase + 6];
    const float* Wf1 = (const float*)d_in[wbase + 7];
    const float* bf1 = (const float*)d_in[wbase + 8];
    const float* Wf2 = (const float*)d_in[wbase + 9];
    const float* bf2 = (const float*)d_in[wbase + 10];
    float* out = (float*)d_out;

    float *p_nf, *p_x1, *p_h1, *p_x2, *p_pool;
    cudaGetSymbolAddress((void**)&p_nf,   g_nf);
    cudaGetSymbolAddress((void**)&p_x1,   g_x1);
    cudaGetSymbolAddress((void**)&p_h1,   g_h1);
    cudaGetSymbolAddress((void**)&p_x2,   g_x2);
    cudaGetSymbolAddress((void**)&p_pool, g_pool);

    const int smem_seg = (NN*256 + SS)*sizeof(float) + SS*sizeof(int);              // 135168
    const int smem_msg = (2*NN*GHD + NN + GHD)*sizeof(float) + 2*EE*sizeof(int);    // 140288
    cudaFuncSetAttribute(k_segsum,     cudaFuncAttributeMaxDynamicSharedMemorySize, smem_seg);
    cudaFuncSetAttribute(k_msg<false>, cudaFuncAttributeMaxDynamicSharedMemorySize, smem_msg);
    cudaFuncSetAttribute(k_msg<true>,  cudaFuncAttributeMaxDynamicSharedMemorySize, smem_msg);

    k_zero<<<8, 1024>>>();
    k_gate<<<(BB*SS*32)/256, 256>>>(lh, submap, wr, br);
    k_segsum<<<dim3(3, BB), 256, smem_seg>>>(lh, submap);
    k_deg<<<BB, 128>>>(ei);
    k_gemm<<<BNN/64, 256>>>(p_nf, W1, p_x1, HH);
    k_msg<false><<<BB, 256, smem_msg>>>(p_x1, b1, ei, p_h1);
    k_gemm<<<BNN/64, 256>>>(p_h1, W2, p_x2, GHD);
    k_msg<true><<<BB, 256, smem_msg>>>(p_x2, b2, ei, p_pool);
    k_fc<<<BB, 256>>>(lh, Wf1, bf1, Wf2, bf2, out);
}

// round 3
// speedup vs baseline: 1.9601x; 1.9601x over previous
#include <cuda_runtime.h>
#include <math.h>

// Problem constants
#define BB  64
#define SS  512
#define HH  768
#define NN  128
#define EE  1024
#define GHD 128
#define FHD 256
#define LL  2
#define BNN (BB*NN)   // 8192

// ---------------- scratch (device globals; no allocation allowed) ----------------
__device__ float g_gate[BB*SS];
__device__ float g_nf[(size_t)BNN*HH];   // 25 MB
__device__ float g_x1[(size_t)BNN*GHD];
__device__ float g_h1[(size_t)BNN*GHD];
__device__ float g_x2[(size_t)BNN*GHD];
__device__ float g_pool[BB*GHD];

// ---------------- cp.async helper ----------------
__device__ __forceinline__ void cp16(void* smem, const void* g) {
    unsigned a = (unsigned)__cvta_generic_to_shared(smem);
    asm volatile("cp.async.cg.shared.global [%0], [%1], 16;\n" :: "r"(a), "l"(g));
}

// ---------------- K1: gate = sigmoid(lh . wr + br) ----------------
__global__ void k_gate(const float* __restrict__ lh,
                       const float* __restrict__ wr, const float* __restrict__ brp) {
    int warp = (blockIdx.x*blockDim.x + threadIdx.x) >> 5;
    int lane = threadIdx.x & 31;
    if (warp >= BB*SS) return;
    const float4* row4 = (const float4*)(lh + (size_t)warp*HH);
    const float4* w4   = (const float4*)wr;
    float dot = 0.f;
    #pragma unroll
    for (int i = 0; i < 6; i++) {
        float4 a = row4[lane + 32*i];
        float4 w = w4[lane + 32*i];
        dot += a.x*w.x + a.y*w.y + a.z*w.z + a.w*w.w;
    }
    #pragma unroll
    for (int off = 16; off; off >>= 1) dot += __shfl_xor_sync(0xffffffffu, dot, off);
    if (lane == 0)
        g_gate[warp] = 1.f/(1.f + expf(-(dot + brp[0])));
}

// ---------------- K2: segment mean (atomic-free; thread-private acc columns) -----
// grid (6, 64), 128 threads, 128-dim chunk per CTA
__global__ void k_segsum(const float* __restrict__ lh, const int* __restrict__ submap) {
    extern __shared__ float sm[];
    float* acc    = sm;                      // NN*128 floats (64 KB)
    float* gate_s = sm + NN*128;             // SS
    float* rc     = gate_s + SS;             // NN
    int*   sub_s  = (int*)(rc + NN);         // SS
    int*   cnt_s  = sub_s + SS;              // NN
    int b = blockIdx.y, c0 = blockIdx.x*128, tid = threadIdx.x;

    for (int i = tid; i < NN*128; i += 128) acc[i] = 0.f;
    if (tid < NN) cnt_s[tid] = 0;
    for (int s = tid; s < SS; s += 128) {
        gate_s[s] = g_gate[b*SS + s];
        sub_s[s]  = submap[b*SS + s];
    }
    __syncthreads();
    for (int s = tid; s < SS; s += 128) atomicAdd(&cnt_s[sub_s[s]], 1);

    const float* base = lh + (size_t)b*SS*HH + c0;
    for (int s0 = 0; s0 < SS; s0 += 8) {
        float v[8];
        #pragma unroll
        for (int j = 0; j < 8; j++)
            v[j] = base[(size_t)(s0+j)*HH + tid];
        #pragma unroll
        for (int j = 0; j < 8; j++) {
            int n = sub_s[s0+j];
            acc[n*128 + tid] += v[j]*gate_s[s0+j];   // thread-private column: no atomic
        }
    }
    __syncthreads();
    if (tid < NN) rc[tid] = 1.f/fmaxf((float)cnt_s[tid], 1.f);
    __syncthreads();
    for (int n = 0; n < NN; n++)
        g_nf[((size_t)(b*NN + n))*HH + c0 + tid] = acc[n*128 + tid]*rc[n];
}

// ---------------- K3/K5: fp32 GEMM  C[BNN x 128] = A[BNN x K] @ W[K x 128] -------
// 64x128 tile, 256 threads, 4x8 per thread, cp.async double-buffered
__global__ void k_gemm(const float* __restrict__ A, const float* __restrict__ W,
                       float* __restrict__ C, int K) {
    __shared__ float As[2][64][20];    // [row][k], pad to 20
    __shared__ float Bs[2][16][128];
    int tid = threadIdx.x;             // 256
    int tx = tid & 15, ty = tid >> 4;
    int row0 = blockIdx.x*64;
    int a_r = tid >> 2,  a_k = (tid & 3)*4;
    int b_r = tid >> 5,  b_c = (tid & 31)*4;
    const float* aP  = A + (size_t)(row0 + a_r)*K + a_k;
    const float* bP0 = W + (size_t)b_r*128 + b_c;
    const float* bP1 = W + (size_t)(b_r + 8)*128 + b_c;

    // prefetch stage 0
    cp16(&As[0][a_r][a_k], aP);
    cp16(&Bs[0][b_r][b_c], bP0);
    cp16(&Bs[0][b_r+8][b_c], bP1);
    asm volatile("cp.async.commit_group;\n" ::: "memory");

    float acc[4][8];
    #pragma unroll
    for (int i = 0; i < 4; i++)
        #pragma unroll
        for (int j = 0; j < 8; j++) acc[i][j] = 0.f;

    int nk = K >> 4;
    for (int kb = 0; kb < nk; kb++) {
        int st = kb & 1;
        if (kb + 1 < nk) {
            int k0 = (kb + 1) << 4;
            cp16(&As[st^1][a_r][a_k], aP + k0);
            cp16(&Bs[st^1][b_r][b_c], bP0 + (size_t)k0*128);
            cp16(&Bs[st^1][b_r+8][b_c], bP1 + (size_t)k0*128);
            asm volatile("cp.async.commit_group;\n" ::: "memory");
            asm volatile("cp.async.wait_group 1;\n" ::: "memory");
        } else {
            asm volatile("cp.async.wait_group 0;\n" ::: "memory");
        }
        __syncthreads();
        #pragma unroll
        for (int kk = 0; kk < 16; kk++) {
            float aa[4];
            #pragma unroll
            for (int i = 0; i < 4; i++) aa[i] = As[st][ty*4 + i][kk];
            float4 bq0 = *(const float4*)&Bs[st][kk][tx*4];
            float4 bq1 = *(const float4*)&Bs[st][kk][64 + tx*4];
            float bb[8] = {bq0.x, bq0.y, bq0.z, bq0.w, bq1.x, bq1.y, bq1.z, bq1.w};
            #pragma unroll
            for (int i = 0; i < 4; i++)
                #pragma unroll
                for (int j = 0; j < 8; j++)
                    acc[i][j] += aa[i]*bb[j];
        }
        __syncthreads();
    }
    #pragma unroll
    for (int i = 0; i < 4; i++) {
        float* cr = C + (size_t)(row0 + ty*4 + i)*128;
        *(float4*)&cr[tx*4]      = make_float4(acc[i][0], acc[i][1], acc[i][2], acc[i][3]);
        *(float4*)&cr[64 + tx*4] = make_float4(acc[i][4], acc[i][5], acc[i][6], acc[i][7]);
    }
}

// ---------------- K4/K6: GCN message passing (warp-sliced, atomic-free scatter) ---
// out[dst] = relu( dinv[dst] * sum_{(src,dst)} (x[src]*dinv[src]) + bias )
template <bool POOL>
__global__ void k_msg(const float* __restrict__ X, const float* __restrict__ bias,
                      const int* __restrict__ ei, float* __restrict__ outp) {
    extern __shared__ float sm[];
    float* hp     = sm;                   // NN*GHD
    float* acc    = sm + NN*GHD;          // NN*GHD
    float* dinv_s = acc + NN*GHD;         // NN  (deg during build)
    float* bias_s = dinv_s + NN;          // GHD
    int*   src_s  = (int*)(bias_s + GHD); // EE
    int*   dst_s  = src_s + EE;           // EE
    int b = blockIdx.x, tid = threadIdx.x; // 256 threads
    int wid = tid >> 5, lane = tid & 31;

    if (tid < NN)  dinv_s[tid] = 1.f;      // self loop
    if (tid < GHD) bias_s[tid] = bias[tid];
    __syncthreads();
    for (int e = tid; e < EE; e += 256) {
        int s = ei[(size_t)b*2*EE + e];
        int d = ei[(size_t)b*2*EE + EE + e];
        src_s[e] = s; dst_s[e] = d;
        atomicAdd(&dinv_s[d], 1.f);        // 1024 tiny smem atomics for degree
    }
    __syncthreads();
    if (tid < NN) dinv_s[tid] = rsqrtf(dinv_s[tid]);
    __syncthreads();

    const float4* X4 = (const float4*)(X + (size_t)b*NN*GHD);
    for (int i = tid; i < NN*GHD/4; i += 256) {
        float4 v = X4[i];
        float dv = dinv_s[i >> 5];
        v.x *= dv; v.y *= dv; v.z *= dv; v.w *= dv;
        *(float4*)&hp[i*4]  = v;
        *(float4*)&acc[i*4] = v;           // acc init = self-loop message
    }
    __syncthreads();

    // warp w owns dst nodes [w*16, w*16+16): no atomics needed
    for (int e0 = 0; e0 < EE; e0 += 32) {
        int dchk = dst_s[e0 + lane];
        unsigned m = __ballot_sync(0xffffffffu, (dchk >> 4) == wid);
        while (m) {
            int i = __ffs(m) - 1; m &= m - 1;
            int e = e0 + i;
            int s = src_s[e], dd = dst_s[e];       // broadcast
            float4 hv = *(const float4*)&hp[s*GHD + lane*4];
            float4* ap = (float4*)&acc[dd*GHD + lane*4];
            float4 a = *ap;
            a.x += hv.x; a.y += hv.y; a.z += hv.z; a.w += hv.w;
            *ap = a;
        }
    }
    __syncthreads();

    if (!POOL) {
        float4* O4 = (float4*)(outp + (size_t)b*NN*GHD);
        for (int i = tid; i < NN*GHD/4; i += 256) {
            float dv = dinv_s[i >> 5];
            int db = (i & 31)*4;
            float4 a = *(float4*)&acc[i*4];
            a.x = fmaxf(a.x*dv + bias_s[db+0], 0.f);
            a.y = fmaxf(a.y*dv + bias_s[db+1], 0.f);
            a.z = fmaxf(a.z*dv + bias_s[db+2], 0.f);
            a.w = fmaxf(a.w*dv + bias_s[db+3], 0.f);
            O4[i] = a;
        }
    } else {
        for (int i = tid; i < NN*GHD/4; i += 256) {
            float dv = dinv_s[i >> 5];
            int db = (i & 31)*4;
            float4 a = *(float4*)&acc[i*4];
            a.x = fmaxf(a.x*dv + bias_s[db+0], 0.f);
            a.y = fmaxf(a.y*dv + bias_s[db+1], 0.f);
            a.z = fmaxf(a.z*dv + bias_s[db+2], 0.f);
            a.w = fmaxf(a.w*dv + bias_s[db+3], 0.f);
            *(float4*)&acc[i*4] = a;
        }
        __syncthreads();
        if (tid < GHD) {
            float ssum = 0.f;
            #pragma unroll 8
            for (int n = 0; n < NN; n++) ssum += acc[n*GHD + tid];
            outp[b*GHD + tid] = ssum * (1.f/NN);
        }
    }
}

// ---------------- K7: final 2-layer MLP ----------------
__global__ void k_fc(const float* __restrict__ lh, const float* __restrict__ Wf1,
                     const float* __restrict__ bf1, const float* __restrict__ Wf2,
                     const float* __restrict__ bf2, float* __restrict__ out) {
    __shared__ float in_s[HH + GHD]; // 896
    __shared__ float hs[FHD];        // 256
    int b = blockIdx.x, tid = threadIdx.x; // 256 threads
    for (int i = tid; i < HH; i += 256) in_s[i] = lh[(size_t)b*SS*HH + i];
    if (tid < GHD) in_s[HH + tid] = g_pool[b*GHD + tid];
    __syncthreads();
    float a = bf1[tid];
    #pragma unroll 8
    for (int k = 0; k < HH + GHD; k++) a += in_s[k]*Wf1[(size_t)k*FHD + tid];
    hs[tid] = fmaxf(a, 0.f);
    __syncthreads();
    if (tid < LL) {
        float o = bf2[tid];
        for (int j = 0; j < FHD; j++) o += hs[j]*Wf2[j*LL + tid];
        out[b*LL + tid] = o;
    }
}

// ---------------- launch ----------------
extern "C" void kernel_launch(void* const* d_in, const int* in_sizes, int n_in,
                              void* d_out, int out_size) {
    const float* lh     = (const float*)d_in[0];
    const int*   submap = (const int*)d_in[1];
    const int*   ei     = (const int*)d_in[2];
    int wbase = (in_sizes[3] == 1) ? 3 : 2;  // num_nodes may be materialized
    const float* wr  = (const float*)d_in[wbase + 1];
    const float* br  = (const float*)d_in[wbase + 2];
    const float* W1  = (const float*)d_in[wbase + 3];
    const float* b1  = (const float*)d_in[wbase + 4];
    const float* W2  = (const float*)d_in[wbase + 5];
    const float* b2  = (const float*)d_in[wbase + 6];
    const float* Wf1 = (const float*)d_in[wbase + 7];
    const float* bf1 = (const float*)d_in[wbase + 8];
    const float* Wf2 = (const float*)d_in[wbase + 9];
    const float* bf2 = (const float*)d_in[wbase + 10];
    float* out = (float*)d_out;

    float *p_nf, *p_x1, *p_h1, *p_x2, *p_pool;
    cudaGetSymbolAddress((void**)&p_nf,   g_nf);
    cudaGetSymbolAddress((void**)&p_x1,   g_x1);
    cudaGetSymbolAddress((void**)&p_h1,   g_h1);
    cudaGetSymbolAddress((void**)&p_x2,   g_x2);
    cudaGetSymbolAddress((void**)&p_pool, g_pool);

    const int smem_seg = (NN*128 + SS + NN)*sizeof(float) + (SS + NN)*sizeof(int); // ~70.7 KB
    const int smem_msg = (2*NN*GHD + NN + GHD)*sizeof(float) + 2*EE*sizeof(int);   // ~137 KB
    cudaFuncSetAttribute(k_segsum,     cudaFuncAttributeMaxDynamicSharedMemorySize, smem_seg);
    cudaFuncSetAttribute(k_msg<false>, cudaFuncAttributeMaxDynamicSharedMemorySize, smem_msg);
    cudaFuncSetAttribute(k_msg<true>,  cudaFuncAttributeMaxDynamicSharedMemorySize, smem_msg);

    k_gate<<<(BB*SS*32)/256, 256>>>(lh, wr, br);
    k_segsum<<<dim3(6, BB), 128, smem_seg>>>(lh, submap);
    k_gemm<<<BNN/64, 256>>>(p_nf, W1, p_x1, HH);
    k_msg<false><<<BB, 256, smem_msg>>>(p_x1, b1, ei, p_h1);
    k_gemm<<<BNN/64, 256>>>(p_h1, W2, p_x2, GHD);
    k_msg<true><<<BB, 256, smem_msg>>>(p_x2, b2, ei, p_pool);
    k_fc<<<BB, 256>>>(lh, Wf1, bf1, Wf2, bf2, out);
}

// round 4
// speedup vs baseline: 2.0388x; 1.0402x over previous
#include <cuda_runtime.h>
#include <math.h>

// Problem constants
#define BB  64
#define SS  512
#define HH  768
#define NN  128
#define EE  1024
#define GHD 128
#define FHD 256
#define LL  2
#define BNN (BB*NN)   // 8192

// ---------------- scratch (device globals; no allocation allowed) ----------------
__device__ float g_gate[BB*SS];
__device__ float g_nf[(size_t)BNN*HH];   // 25 MB
__device__ float g_x1[(size_t)BNN*GHD];
__device__ float g_h1[(size_t)BNN*GHD];
__device__ float g_x2[(size_t)BNN*GHD];
__device__ float g_pool[BB*GHD];

// ---------------- helpers ----------------
__device__ __forceinline__ void cp16(void* smem, const void* g) {
    unsigned a = (unsigned)__cvta_generic_to_shared(smem);
    asm volatile("cp.async.cg.shared.global [%0], [%1], 16;\n" :: "r"(a), "l"(g));
}
__device__ __forceinline__ unsigned long long dup2(float a) {
    unsigned long long r;
    asm("mov.b64 %0, {%1, %1};" : "=l"(r) : "f"(a));
    return r;
}
__device__ __forceinline__ void ffma2(unsigned long long& d, unsigned long long a,
                                      unsigned long long b) {
    asm("fma.rn.f32x2 %0, %1, %2, %0;" : "+l"(d) : "l"(a), "l"(b));
}

// ---------------- K1: gate = sigmoid(lh . wr + br) ----------------
__global__ void k_gate(const float* __restrict__ lh,
                       const float* __restrict__ wr, const float* __restrict__ brp) {
    int warp = (blockIdx.x*blockDim.x + threadIdx.x) >> 5;
    int lane = threadIdx.x & 31;
    if (warp >= BB*SS) return;
    const float4* row4 = (const float4*)(lh + (size_t)warp*HH);
    const float4* w4   = (const float4*)wr;
    float dot = 0.f;
    #pragma unroll
    for (int i = 0; i < 6; i++) {
        float4 a = row4[lane + 32*i];
        float4 w = w4[lane + 32*i];
        dot += a.x*w.x + a.y*w.y + a.z*w.z + a.w*w.w;
    }
    #pragma unroll
    for (int off = 16; off; off >>= 1) dot += __shfl_xor_sync(0xffffffffu, dot, off);
    if (lane == 0)
        g_gate[warp] = 1.f/(1.f + expf(-(dot + brp[0])));
}

// ---------------- K2: segment mean (atomic-free; thread-private acc columns) -----
// grid (6, 64), 128 threads, 128-dim chunk per CTA
__global__ void k_segsum(const float* __restrict__ lh, const int* __restrict__ submap) {
    extern __shared__ float sm[];
    float* acc    = sm;                      // NN*128 floats (64 KB)
    float* gate_s = sm + NN*128;             // SS
    float* rc     = gate_s + SS;             // NN
    int*   sub_s  = (int*)(rc + NN);         // SS
    int*   cnt_s  = sub_s + SS;              // NN
    int b = blockIdx.y, c0 = blockIdx.x*128, tid = threadIdx.x;

    for (int i = tid; i < NN*128; i += 128) acc[i] = 0.f;
    if (tid < NN) cnt_s[tid] = 0;
    for (int s = tid; s < SS; s += 128) {
        gate_s[s] = g_gate[b*SS + s];
        sub_s[s]  = submap[b*SS + s];
    }
    __syncthreads();
    for (int s = tid; s < SS; s += 128) atomicAdd(&cnt_s[sub_s[s]], 1);

    const float* base = lh + (size_t)b*SS*HH + c0;
    for (int s0 = 0; s0 < SS; s0 += 8) {
        float v[8];
        #pragma unroll
        for (int j = 0; j < 8; j++)
            v[j] = base[(size_t)(s0+j)*HH + tid];
        #pragma unroll
        for (int j = 0; j < 8; j++) {
            int n = sub_s[s0+j];
            acc[n*128 + tid] += v[j]*gate_s[s0+j];   // thread-private column
        }
    }
    __syncthreads();
    if (tid < NN) rc[tid] = 1.f/fmaxf((float)cnt_s[tid], 1.f);
    __syncthreads();
    for (int n = 0; n < NN; n++)
        g_nf[((size_t)(b*NN + n))*HH + c0 + tid] = acc[n*128 + tid]*rc[n];
}

// ---------------- K3/K5: fp32 GEMM with packed FFMA2 -----------------------------
// C[BNN x 128] = A[BNN x K] @ W[K x 128]; 64x128 tile, 256 threads, 4x8 per thread
__global__ void k_gemm(const float* __restrict__ A, const float* __restrict__ W,
                       float* __restrict__ C, int K) {
    __shared__ float As[2][64][20];    // [row][k], pad to 20
    __shared__ float Bs[2][16][128];
    int tid = threadIdx.x;             // 256
    int tx = tid & 15, ty = tid >> 4;
    int row0 = blockIdx.x*64;
    int a_r = tid >> 2,  a_k = (tid & 3)*4;
    int b_r = tid >> 5,  b_c = (tid & 31)*4;
    const float* aP  = A + (size_t)(row0 + a_r)*K + a_k;
    const float* bP0 = W + (size_t)b_r*128 + b_c;
    const float* bP1 = W + (size_t)(b_r + 8)*128 + b_c;

    cp16(&As[0][a_r][a_k], aP);
    cp16(&Bs[0][b_r][b_c], bP0);
    cp16(&Bs[0][b_r+8][b_c], bP1);
    asm volatile("cp.async.commit_group;\n" ::: "memory");

    unsigned long long acc[4][4];      // 4 rows x 4 col-pairs (f32x2)
    #pragma unroll
    for (int i = 0; i < 4; i++)
        #pragma unroll
        for (int j = 0; j < 4; j++) acc[i][j] = 0ull;

    int nk = K >> 4;
    for (int kb = 0; kb < nk; kb++) {
        int st = kb & 1;
        if (kb + 1 < nk) {
            int k0 = (kb + 1) << 4;
            cp16(&As[st^1][a_r][a_k], aP + k0);
            cp16(&Bs[st^1][b_r][b_c], bP0 + (size_t)k0*128);
            cp16(&Bs[st^1][b_r+8][b_c], bP1 + (size_t)k0*128);
            asm volatile("cp.async.commit_group;\n" ::: "memory");
            asm volatile("cp.async.wait_group 1;\n" ::: "memory");
        } else {
            asm volatile("cp.async.wait_group 0;\n" ::: "memory");
        }
        __syncthreads();
        #pragma unroll
        for (int kk = 0; kk < 16; kk++) {
            ulonglong2 b01 = *(const ulonglong2*)&Bs[st][kk][tx*4];
            ulonglong2 b23 = *(const ulonglong2*)&Bs[st][kk][64 + tx*4];
            #pragma unroll
            for (int i = 0; i < 4; i++) {
                unsigned long long ad = dup2(As[st][ty*4 + i][kk]);
                ffma2(acc[i][0], ad, b01.x);
                ffma2(acc[i][1], ad, b01.y);
                ffma2(acc[i][2], ad, b23.x);
                ffma2(acc[i][3], ad, b23.y);
            }
        }
        __syncthreads();
    }
    #pragma unroll
    for (int i = 0; i < 4; i++) {
        float* cr = C + (size_t)(row0 + ty*4 + i)*128;
        float2 p0 = *(float2*)&acc[i][0];
        float2 p1 = *(float2*)&acc[i][1];
        float2 p2 = *(float2*)&acc[i][2];
        float2 p3 = *(float2*)&acc[i][3];
        *(float4*)&cr[tx*4]      = make_float4(p0.x, p0.y, p1.x, p1.y);
        *(float4*)&cr[64 + tx*4] = make_float4(p2.x, p2.y, p3.x, p3.y);
    }
}

// ---------------- K4/K6: GCN message passing (dim-split, atomic-free scatter) -----
// grid = BB*4; each CTA handles batch b = blockIdx.x>>2, dims [c0, c0+32)
// out[dst] = relu( dinv[dst] * sum_{(src,dst)} (x[src]*dinv[src]) + bias )
template <bool POOL>
__global__ void k_msg(const float* __restrict__ X, const float* __restrict__ bias,
                      const int* __restrict__ ei, float* __restrict__ outp) {
    extern __shared__ float sm[];
    float* hp     = sm;                   // NN*32
    float* acc    = sm + NN*32;           // NN*32
    float* dinv_s = acc + NN*32;          // NN
    float* bias_s = dinv_s + NN;          // 32
    int*   src_s  = (int*)(bias_s + 32);  // EE
    int*   dst_s  = src_s + EE;           // EE
    int b  = blockIdx.x >> 2;
    int c0 = (blockIdx.x & 3)*32;
    int tid = threadIdx.x;                // 256 threads
    int wid = tid >> 5, lane = tid & 31;

    if (tid < NN) dinv_s[tid] = 1.f;      // self loop
    if (tid < 32) bias_s[tid] = bias[c0 + tid];
    __syncthreads();
    for (int e = tid; e < EE; e += 256) {
        int s = ei[(size_t)b*2*EE + e];
        int d = ei[(size_t)b*2*EE + EE + e];
        src_s[e] = s; dst_s[e] = d;
        atomicAdd(&dinv_s[d], 1.f);
    }
    __syncthreads();
    if (tid < NN) dinv_s[tid] = rsqrtf(dinv_s[tid]);
    __syncthreads();

    const float* Xb = X + (size_t)b*NN*GHD + c0;
    for (int i = tid; i < NN*32; i += 256) {
        int n = i >> 5, d = i & 31;
        float v = Xb[(size_t)n*GHD + d] * dinv_s[n];
        hp[i] = v; acc[i] = v;            // acc init = self-loop message
    }
    __syncthreads();

    // warp w owns dst nodes [w*16, w*16+16); lane owns one dim: no atomics
    for (int e0 = 0; e0 < EE; e0 += 32) {
        int dchk = dst_s[e0 + lane];
        int schk = src_s[e0 + lane];
        unsigned m = __ballot_sync(0xffffffffu, (dchk >> 4) == wid);
        while (m) {
            int i = __ffs(m) - 1; m &= m - 1;
            int s  = __shfl_sync(0xffffffffu, schk, i);
            int dd = __shfl_sync(0xffffffffu, dchk, i);
            acc[dd*32 + lane] += hp[s*32 + lane];
        }
    }
    __syncthreads();

    if (!POOL) {
        float* Ob = outp + (size_t)b*NN*GHD + c0;
        for (int i = tid; i < NN*32; i += 256) {
            int n = i >> 5, d = i & 31;
            Ob[(size_t)n*GHD + d] = fmaxf(acc[i]*dinv_s[n] + bias_s[d], 0.f);
        }
    } else {
        for (int i = tid; i < NN*32; i += 256) {
            int n = i >> 5, d = i & 31;
            acc[i] = fmaxf(acc[i]*dinv_s[n] + bias_s[d], 0.f);
        }
        __syncthreads();
        if (tid < 32) {
            float ssum = 0.f;
            #pragma unroll 8
            for (int n = 0; n < NN; n++) ssum += acc[n*32 + tid];
            outp[b*GHD + c0 + tid] = ssum * (1.f/NN);
        }
    }
}

// ---------------- K7: final 2-layer MLP ----------------
__global__ void k_fc(const float* __restrict__ lh, const float* __restrict__ Wf1,
                     const float* __restrict__ bf1, const float* __restrict__ Wf2,
                     const float* __restrict__ bf2, float* __restrict__ out) {
    __shared__ float in_s[HH + GHD]; // 896
    __shared__ float hs[FHD];        // 256
    int b = blockIdx.x, tid = threadIdx.x; // 256 threads
    for (int i = tid; i < HH; i += 256) in_s[i] = lh[(size_t)b*SS*HH + i];
    if (tid < GHD) in_s[HH + tid] = g_pool[b*GHD + tid];
    __syncthreads();
    float a = bf1[tid];
    #pragma unroll 8
    for (int k = 0; k < HH + GHD; k++) a += in_s[k]*Wf1[(size_t)k*FHD + tid];
    hs[tid] = fmaxf(a, 0.f);
    __syncthreads();
    if (tid < LL) {
        float o = bf2[tid];
        for (int j = 0; j < FHD; j++) o += hs[j]*Wf2[j*LL + tid];
        out[b*LL + tid] = o;
    }
}

// ---------------- launch ----------------
extern "C" void kernel_launch(void* const* d_in, const int* in_sizes, int n_in,
                              void* d_out, int out_size) {
    const float* lh     = (const float*)d_in[0];
    const int*   submap = (const int*)d_in[1];
    const int*   ei     = (const int*)d_in[2];
    int wbase = (in_sizes[3] == 1) ? 3 : 2;  // num_nodes may be materialized
    const float* wr  = (const float*)d_in[wbase + 1];
    const float* br  = (const float*)d_in[wbase + 2];
    const float* W1  = (const float*)d_in[wbase + 3];
    const float* b1  = (const float*)d_in[wbase + 4];
    const float* W2  = (const float*)d_in[wbase + 5];
    const float* b2  = (const float*)d_in[wbase + 6];
    const float* Wf1 = (const float*)d_in[wbase + 7];
    const float* bf1 = (const float*)d_in[wbase + 8];
    const float* Wf2 = (const float*)d_in[wbase + 9];
    const float* bf2 = (const float*)d_in[wbase + 10];
    float* out = (float*)d_out;

    float *p_nf, *p_x1, *p_h1, *p_x2, *p_pool;
    cudaGetSymbolAddress((void**)&p_nf,   g_nf);
    cudaGetSymbolAddress((void**)&p_x1,   g_x1);
    cudaGetSymbolAddress((void**)&p_h1,   g_h1);
    cudaGetSymbolAddress((void**)&p_x2,   g_x2);
    cudaGetSymbolAddress((void**)&p_pool, g_pool);

    const int smem_seg = (NN*128 + SS + NN)*sizeof(float) + (SS + NN)*sizeof(int); // ~70.7 KB
    const int smem_msg = (2*NN*32 + NN + 32)*sizeof(float) + 2*EE*sizeof(int);     // ~41 KB
    cudaFuncSetAttribute(k_segsum,     cudaFuncAttributeMaxDynamicSharedMemorySize, smem_seg);
    cudaFuncSetAttribute(k_msg<false>, cudaFuncAttributeMaxDynamicSharedMemorySize, smem_msg);
    cudaFuncSetAttribute(k_msg<true>,  cudaFuncAttributeMaxDynamicSharedMemorySize, smem_msg);

    k_gate<<<(BB*SS*32)/256, 256>>>(lh, wr, br);
    k_segsum<<<dim3(6, BB), 128, smem_seg>>>(lh, submap);
    k_gemm<<<BNN/64, 256>>>(p_nf, W1, p_x1, HH);
    k_msg<false><<<BB*4, 256, smem_msg>>>(p_x1, b1, ei, p_h1);
    k_gemm<<<BNN/64, 256>>>(p_h1, W2, p_x2, GHD);
    k_msg<true><<<BB*4, 256, smem_msg>>>(p_x2, b2, ei, p_pool);
    k_fc<<<BB, 256>>>(lh, Wf1, bf1, Wf2, bf2, out);
}

// round 5
// speedup vs baseline: 2.0709x; 1.0157x over previous
#include <cuda_runtime.h>
#include <math.h>

// Problem constants
#define BB  64
#define SS  512
#define HH  768
#define NN  128
#define EE  1024
#define GHD 128
#define FHD 256
#define LL  2
#define BNN (BB*NN)   // 8192

// ---------------- scratch (device globals; no allocation allowed) ----------------
__device__ float g_gate[BB*SS];
__device__ float g_nf[(size_t)BNN*HH];        // 25 MB
__device__ float g_adjT[(size_t)BB*NN*NN];    // 4 MB, [b][s][d] (transposed)
__device__ float g_x1[(size_t)BNN*GHD];
__device__ float g_h1[(size_t)BNN*GHD];
__device__ float g_x2[(size_t)BNN*GHD];
__device__ float g_pool[BB*GHD];

// ---------------- helpers ----------------
__device__ __forceinline__ void cp16(void* smem, const void* g) {
    unsigned a = (unsigned)__cvta_generic_to_shared(smem);
    asm volatile("cp.async.cg.shared.global [%0], [%1], 16;\n" :: "r"(a), "l"(g));
}
__device__ __forceinline__ unsigned long long dup2(float a) {
    unsigned long long r;
    asm("mov.b64 %0, {%1, %1};" : "=l"(r) : "f"(a));
    return r;
}
__device__ __forceinline__ void ffma2(unsigned long long& d, unsigned long long a,
                                      unsigned long long b) {
    asm("fma.rn.f32x2 %0, %1, %2, %0;" : "+l"(d) : "l"(a), "l"(b));
}

// ---------------- K1: gate = sigmoid(lh . wr + br) ----------------
__global__ void k_gate(const float* __restrict__ lh,
                       const float* __restrict__ wr, const float* __restrict__ brp) {
    int warp = (blockIdx.x*blockDim.x + threadIdx.x) >> 5;
    int lane = threadIdx.x & 31;
    if (warp >= BB*SS) return;
    const float4* row4 = (const float4*)(lh + (size_t)warp*HH);
    const float4* w4   = (const float4*)wr;
    float dot = 0.f;
    #pragma unroll
    for (int i = 0; i < 6; i++) {
        float4 a = row4[lane + 32*i];
        float4 w = w4[lane + 32*i];
        dot += a.x*w.x + a.y*w.y + a.z*w.z + a.w*w.w;
    }
    #pragma unroll
    for (int off = 16; off; off >>= 1) dot += __shfl_xor_sync(0xffffffffu, dot, off);
    if (lane == 0)
        g_gate[warp] = 1.f/(1.f + expf(-(dot + brp[0])));
}

// ---------------- K2: segment mean (atomic-free; thread-private acc columns) -----
// grid (6, 64), 128 threads, 128-dim chunk per CTA
__global__ void k_segsum(const float* __restrict__ lh, const int* __restrict__ submap) {
    extern __shared__ float sm[];
    float* acc    = sm;                      // NN*128 floats (64 KB)
    float* gate_s = sm + NN*128;             // SS
    float* rc     = gate_s + SS;             // NN
    int*   sub_s  = (int*)(rc + NN);         // SS
    int*   cnt_s  = sub_s + SS;              // NN
    int b = blockIdx.y, c0 = blockIdx.x*128, tid = threadIdx.x;

    for (int i = tid; i < NN*128; i += 128) acc[i] = 0.f;
    if (tid < NN) cnt_s[tid] = 0;
    for (int s = tid; s < SS; s += 128) {
        gate_s[s] = g_gate[b*SS + s];
        sub_s[s]  = submap[b*SS + s];
    }
    __syncthreads();
    for (int s = tid; s < SS; s += 128) atomicAdd(&cnt_s[sub_s[s]], 1);

    const float* base = lh + (size_t)b*SS*HH + c0;
    for (int s0 = 0; s0 < SS; s0 += 8) {
        float v[8];
        #pragma unroll
        for (int j = 0; j < 8; j++)
            v[j] = base[(size_t)(s0+j)*HH + tid];
        #pragma unroll
        for (int j = 0; j < 8; j++) {
            int n = sub_s[s0+j];
            acc[n*128 + tid] += v[j]*gate_s[s0+j];   // thread-private column
        }
    }
    __syncthreads();
    if (tid < NN) rc[tid] = 1.f/fmaxf((float)cnt_s[tid], 1.f);
    __syncthreads();
    for (int n = 0; n < NN; n++)
        g_nf[((size_t)(b*NN + n))*HH + c0 + tid] = acc[n*128 + tid]*rc[n];
}

// ---------------- K3: build dense normalized adjacency (transposed) ---------------
// g_adjT[b][s][d] = (count(s->d) + (s==d)) * dinv[d] * dinv[s]
__global__ void k_adj(const int* __restrict__ ei) {
    extern __shared__ float sm[];
    float* cnt = sm;          // NN*NN, indexed [s][d]
    float* deg = sm + NN*NN;  // NN
    int b = blockIdx.x, tid = threadIdx.x;   // 256 threads
    float4* c4 = (float4*)cnt;
    for (int i = tid; i < NN*NN/4; i += 256) c4[i] = make_float4(0.f,0.f,0.f,0.f);
    if (tid < NN) deg[tid] = 1.f;   // self loop
    __syncthreads();
    const int* sP = ei + (size_t)b*2*EE;
    const int* dP = sP + EE;
    for (int e = tid; e < EE; e += 256) {
        int s = sP[e], d = dP[e];
        atomicAdd(&deg[d], 1.f);
        atomicAdd(&cnt[s*NN + d], 1.f);
    }
    __syncthreads();
    if (tid < NN) deg[tid] = rsqrtf(deg[tid]);
    __syncthreads();
    float* outp = g_adjT + (size_t)b*NN*NN;
    for (int i = tid; i < NN*NN; i += 256) {
        int s = i >> 7, d = i & 127;
        float v = cnt[i] + (s == d ? 1.f : 0.f);
        outp[i] = v * deg[d] * deg[s];
    }
}

// ---------------- K4/K6: fp32 GEMM (k-major A smem, conflict-free; FFMA2) --------
// C[BNN x 128] = A[BNN x K] @ W[K x 128]; 64x128 tile, 256 threads, 4x8 per thread
__global__ void k_gemm(const float* __restrict__ A, const float* __restrict__ W,
                       float* __restrict__ C, int K) {
    __shared__ float As[2][16][68];    // [k][row], padded
    __shared__ float Bs[2][16][128];
    int tid = threadIdx.x;             // 256
    int tx = tid & 15, ty = tid >> 4;
    int row0 = blockIdx.x*64;
    int a_r = tid >> 2,  a_k = (tid & 3)*4;
    int b_r = tid >> 5,  b_c = (tid & 31)*4;
    const float* aP  = A + (size_t)(row0 + a_r)*K + a_k;
    const float* bP0 = W + (size_t)b_r*128 + b_c;
    const float* bP1 = W + (size_t)(b_r + 8)*128 + b_c;

    float4 aReg = *(const float4*)aP;
    cp16(&Bs[0][b_r][b_c], bP0);
    cp16(&Bs[0][b_r+8][b_c], bP1);
    asm volatile("cp.async.commit_group;\n" ::: "memory");

    unsigned long long acc[4][4];      // 4 rows x 4 col-pairs (f32x2)
    #pragma unroll
    for (int i = 0; i < 4; i++)
        #pragma unroll
        for (int j = 0; j < 4; j++) acc[i][j] = 0ull;

    int nk = K >> 4;
    for (int kb = 0; kb < nk; kb++) {
        int st = kb & 1;
        // stage A into k-major smem (register-staged transpose)
        As[st][a_k+0][a_r] = aReg.x;
        As[st][a_k+1][a_r] = aReg.y;
        As[st][a_k+2][a_r] = aReg.z;
        As[st][a_k+3][a_r] = aReg.w;
        float4 aNext;
        if (kb + 1 < nk) {
            int k0 = (kb + 1) << 4;
            aNext = *(const float4*)(aP + k0);
            cp16(&Bs[st^1][b_r][b_c], bP0 + (size_t)k0*128);
            cp16(&Bs[st^1][b_r+8][b_c], bP1 + (size_t)k0*128);
            asm volatile("cp.async.commit_group;\n" ::: "memory");
            asm volatile("cp.async.wait_group 1;\n" ::: "memory");
        } else {
            asm volatile("cp.async.wait_group 0;\n" ::: "memory");
        }
        __syncthreads();
        #pragma unroll
        for (int kk = 0; kk < 16; kk++) {
            float4 aq = *(const float4*)&As[st][kk][ty*4];          // 1 LDS.128
            ulonglong2 b01 = *(const ulonglong2*)&Bs[st][kk][tx*4];
            ulonglong2 b23 = *(const ulonglong2*)&Bs[st][kk][64 + tx*4];
            unsigned long long a0 = dup2(aq.x), a1 = dup2(aq.y);
            unsigned long long a2 = dup2(aq.z), a3 = dup2(aq.w);
            ffma2(acc[0][0], a0, b01.x); ffma2(acc[0][1], a0, b01.y);
            ffma2(acc[0][2], a0, b23.x); ffma2(acc[0][3], a0, b23.y);
            ffma2(acc[1][0], a1, b01.x); ffma2(acc[1][1], a1, b01.y);
            ffma2(acc[1][2], a1, b23.x); ffma2(acc[1][3], a1, b23.y);
            ffma2(acc[2][0], a2, b01.x); ffma2(acc[2][1], a2, b01.y);
            ffma2(acc[2][2], a2, b23.x); ffma2(acc[2][3], a2, b23.y);
            ffma2(acc[3][0], a3, b01.x); ffma2(acc[3][1], a3, b01.y);
            ffma2(acc[3][2], a3, b23.x); ffma2(acc[3][3], a3, b23.y);
        }
        __syncthreads();
        aReg = aNext;
    }
    #pragma unroll
    for (int i = 0; i < 4; i++) {
        float* cr = C + (size_t)(row0 + ty*4 + i)*128;
        float2 p0 = *(float2*)&acc[i][0];
        float2 p1 = *(float2*)&acc[i][1];
        float2 p2 = *(float2*)&acc[i][2];
        float2 p3 = *(float2*)&acc[i][3];
        *(float4*)&cr[tx*4]      = make_float4(p0.x, p0.y, p1.x, p1.y);
        *(float4*)&cr[64 + tx*4] = make_float4(p2.x, p2.y, p3.x, p3.y);
    }
}

// ---------------- K5/K7: GCN aggregation as dense batched GEMM -------------------
// out[d][c] = relu( sum_s AdjT[s][d] * X[s][c] + bias[c] );  grid = BB*2 (c-halves)
template <bool POOL>
__global__ void k_ah(const float* __restrict__ X, const float* __restrict__ bias,
                     float* __restrict__ outp) {
    extern __shared__ float sm[];
    float* At     = sm;                 // NN*NN  (64 KB), [s][d]
    float* Hs     = sm + NN*NN;         // NN*64  (32 KB), [s][c]
    float* red    = Hs + NN*64;         // 16*64  (4 KB, POOL reduce)
    float* bias_s = red + 16*64;        // 64
    int bx = blockIdx.x;
    int b = bx >> 1, c0 = (bx & 1)*64;
    int tid = threadIdx.x;              // 256
    int tx = tid & 15, ty = tid >> 4;

    const float4* aSrc = (const float4*)(g_adjT + (size_t)b*NN*NN);
    float4* aDst = (float4*)At;
    for (int i = tid; i < NN*NN/4; i += 256) aDst[i] = aSrc[i];
    const float* Xb = X + (size_t)b*NN*GHD + c0;
    for (int i = tid; i < NN*16; i += 256) {
        int s = i >> 4, c = (i & 15)*4;
        *(float4*)&Hs[s*64 + c] = *(const float4*)&Xb[(size_t)s*GHD + c];
    }
    if (tid < 64) bias_s[tid] = bias[c0 + tid];
    __syncthreads();

    // thread computes rows d = ty*8..+7, cols c = tx*4..+3
    unsigned long long acc[8][2];
    #pragma unroll
    for (int r = 0; r < 8; r++) { acc[r][0] = 0ull; acc[r][1] = 0ull; }

    #pragma unroll 4
    for (int s = 0; s < NN; s++) {
        float4 a0 = *(const float4*)&At[s*NN + ty*8];
        float4 a1 = *(const float4*)&At[s*NN + ty*8 + 4];
        ulonglong2 h = *(const ulonglong2*)&Hs[s*64 + tx*4];
        unsigned long long d0 = dup2(a0.x), d1 = dup2(a0.y), d2 = dup2(a0.z), d3 = dup2(a0.w);
        unsigned long long d4 = dup2(a1.x), d5 = dup2(a1.y), d6 = dup2(a1.z), d7 = dup2(a1.w);
        ffma2(acc[0][0], d0, h.x); ffma2(acc[0][1], d0, h.y);
        ffma2(acc[1][0], d1, h.x); ffma2(acc[1][1], d1, h.y);
        ffma2(acc[2][0], d2, h.x); ffma2(acc[2][1], d2, h.y);
        ffma2(acc[3][0], d3, h.x); ffma2(acc[3][1], d3, h.y);
        ffma2(acc[4][0], d4, h.x); ffma2(acc[4][1], d4, h.y);
        ffma2(acc[5][0], d5, h.x); ffma2(acc[5][1], d5, h.y);
        ffma2(acc[6][0], d6, h.x); ffma2(acc[6][1], d6, h.y);
        ffma2(acc[7][0], d7, h.x); ffma2(acc[7][1], d7, h.y);
    }

    float bb0 = bias_s[tx*4+0], bb1 = bias_s[tx*4+1];
    float bb2 = bias_s[tx*4+2], bb3 = bias_s[tx*4+3];
    float ps0 = 0.f, ps1 = 0.f, ps2 = 0.f, ps3 = 0.f;
    #pragma unroll
    for (int r = 0; r < 8; r++) {
        float2 p0 = *(float2*)&acc[r][0];
        float2 p1 = *(float2*)&acc[r][1];
        float v0 = fmaxf(p0.x + bb0, 0.f);
        float v1 = fmaxf(p0.y + bb1, 0.f);
        float v2 = fmaxf(p1.x + bb2, 0.f);
        float v3 = fmaxf(p1.y + bb3, 0.f);
        if (!POOL) {
            int d = ty*8 + r;
            *(float4*)&outp[(size_t)b*NN*GHD + (size_t)d*GHD + c0 + tx*4] =
                make_float4(v0, v1, v2, v3);
        } else {
            ps0 += v0; ps1 += v1; ps2 += v2; ps3 += v3;
        }
    }
    if (POOL) {
        *(float4*)&red[ty*64 + tx*4] = make_float4(ps0, ps1, ps2, ps3);
        __syncthreads();
        if (tid < 64) {
            float ssum = 0.f;
            #pragma unroll
            for (int g = 0; g < 16; g++) ssum += red[g*64 + tid];
            outp[b*GHD + c0 + tid] = ssum * (1.f/NN);
        }
    }
}

// ---------------- K8: final 2-layer MLP ----------------
__global__ void k_fc(const float* __restrict__ lh, const float* __restrict__ Wf1,
                     const float* __restrict__ bf1, const float* __restrict__ Wf2,
                     const float* __restrict__ bf2, float* __restrict__ out) {
    __shared__ float in_s[HH + GHD]; // 896
    __shared__ float hs[FHD];        // 256
    int b = blockIdx.x, tid = threadIdx.x; // 256 threads
    for (int i = tid; i < HH; i += 256) in_s[i] = lh[(size_t)b*SS*HH + i];
    if (tid < GHD) in_s[HH + tid] = g_pool[b*GHD + tid];
    __syncthreads();
    float a = bf1[tid];
    #pragma unroll 8
    for (int k = 0; k < HH + GHD; k++) a += in_s[k]*Wf1[(size_t)k*FHD + tid];
    hs[tid] = fmaxf(a, 0.f);
    __syncthreads();
    if (tid < LL) {
        float o = bf2[tid];
        for (int j = 0; j < FHD; j++) o += hs[j]*Wf2[j*LL + tid];
        out[b*LL + tid] = o;
    }
}

// ---------------- launch ----------------
extern "C" void kernel_launch(void* const* d_in, const int* in_sizes, int n_in,
                              void* d_out, int out_size) {
    const float* lh     = (const float*)d_in[0];
    const int*   submap = (const int*)d_in[1];
    const int*   ei     = (const int*)d_in[2];
    int wbase = (in_sizes[3] == 1) ? 3 : 2;  // num_nodes may be materialized
    const float* wr  = (const float*)d_in[wbase + 1];
    const float* br  = (const float*)d_in[wbase + 2];
    const float* W1  = (const float*)d_in[wbase + 3];
    const float* b1  = (const float*)d_in[wbase + 4];
    const float* W2  = (const float*)d_in[wbase + 5];
    const float* b2  = (const float*)d_in[wbase + 6];
    const float* Wf1 = (const float*)d_in[wbase + 7];
    const float* bf1 = (const float*)d_in[wbase + 8];
    const float* Wf2 = (const float*)d_in[wbase + 9];
    const float* bf2 = (const float*)d_in[wbase + 10];
    float* out = (float*)d_out;

    float *p_nf, *p_x1, *p_h1, *p_x2, *p_pool;
    cudaGetSymbolAddress((void**)&p_nf,   g_nf);
    cudaGetSymbolAddress((void**)&p_x1,   g_x1);
    cudaGetSymbolAddress((void**)&p_h1,   g_h1);
    cudaGetSymbolAddress((void**)&p_x2,   g_x2);
    cudaGetSymbolAddress((void**)&p_pool, g_pool);

    const int smem_seg = (NN*128 + SS + NN)*sizeof(float) + (SS + NN)*sizeof(int); // ~70.7 KB
    const int smem_adj = (NN*NN + NN)*sizeof(float);                                // ~66 KB
    const int smem_ah  = (NN*NN + NN*64 + 16*64 + 64)*sizeof(float);                // ~100.5 KB
    cudaFuncSetAttribute(k_segsum,    cudaFuncAttributeMaxDynamicSharedMemorySize, smem_seg);
    cudaFuncSetAttribute(k_adj,       cudaFuncAttributeMaxDynamicSharedMemorySize, smem_adj);
    cudaFuncSetAttribute(k_ah<false>, cudaFuncAttributeMaxDynamicSharedMemorySize, smem_ah);
    cudaFuncSetAttribute(k_ah<true>,  cudaFuncAttributeMaxDynamicSharedMemorySize, smem_ah);

    k_gate<<<(BB*SS*32)/256, 256>>>(lh, wr, br);
    k_segsum<<<dim3(6, BB), 128, smem_seg>>>(lh, submap);
    k_adj<<<BB, 256, smem_adj>>>(ei);
    k_gemm<<<BNN/64, 256>>>(p_nf, W1, p_x1, HH);
    k_ah<false><<<BB*2, 256, smem_ah>>>(p_x1, b1, p_h1);
    k_gemm<<<BNN/64, 256>>>(p_h1, W2, p_x2, GHD);
    k_ah<true><<<BB*2, 256, smem_ah>>>(p_x2, b2, p_pool);
    k_fc<<<BB, 256>>>(lh, Wf1, bf1, Wf2, bf2, out);
}

// round 7
// speedup vs baseline: 2.1219x; 1.0246x over previous
#include <cuda_runtime.h>
#include <math.h>

// Problem constants
#define BB  64
#define SS  512
#define HH  768
#define NN  128
#define EE  1024
#define GHD 128
#define FHD 256
#define LL  2
#define BNN (BB*NN)   // 8192
#define STG 6         // segsum pipeline depth

// ---------------- scratch (device globals; no allocation allowed) ----------------
__device__ float g_gate[BB*SS];
__device__ float g_nf[(size_t)BNN*HH];        // 25 MB
__device__ float g_adjT[(size_t)BB*NN*NN];    // 4 MB, [b][s][d]
__device__ float g_x1[(size_t)BNN*GHD];
__device__ float g_h1[(size_t)BNN*GHD];
__device__ float g_x2[(size_t)BNN*GHD];
__device__ float g_pool[BB*GHD];

// ---------------- helpers ----------------
__device__ __forceinline__ void cp16(void* smem, const void* g) {
    unsigned a = (unsigned)__cvta_generic_to_shared(smem);
    asm volatile("cp.async.cg.shared.global [%0], [%1], 16;\n" :: "r"(a), "l"(g));
}
__device__ __forceinline__ unsigned long long dup2(float a) {
    unsigned long long r;
    asm("mov.b64 %0, {%1, %1};" : "=l"(r) : "f"(a));
    return r;
}
__device__ __forceinline__ void ffma2(unsigned long long& d, unsigned long long a,
                                      unsigned long long b) {
    asm("fma.rn.f32x2 %0, %1, %2, %0;" : "+l"(d) : "l"(a), "l"(b));
}

// ---------------- K1: gate = sigmoid(lh . wr + br) ----------------
__global__ void k_gate(const float* __restrict__ lh,
                       const float* __restrict__ wr, const float* __restrict__ brp) {
    int warp = (blockIdx.x*blockDim.x + threadIdx.x) >> 5;
    int lane = threadIdx.x & 31;
    if (warp >= BB*SS) return;
    const float4* row4 = (const float4*)(lh + (size_t)warp*HH);
    const float4* w4   = (const float4*)wr;
    float dot = 0.f;
    #pragma unroll
    for (int i = 0; i < 6; i++) {
        float4 a = row4[lane + 32*i];
        float4 w = w4[lane + 32*i];
        dot += a.x*w.x + a.y*w.y + a.z*w.z + a.w*w.w;
    }
    #pragma unroll
    for (int off = 16; off; off >>= 1) dot += __shfl_xor_sync(0xffffffffu, dot, off);
    if (lane == 0)
        g_gate[warp] = 1.f/(1.f + expf(-(dot + brp[0])));
}

// ---------------- K2: segment mean — cp.async streaming, thread-private columns ---
// grid (6, 64), 128 threads; CTA = (batch b, 128-dim chunk c0)
__global__ void k_segsum(const float* __restrict__ lh, const int* __restrict__ submap) {
    extern __shared__ float sm[];
    float* acc    = sm;                       // NN*128 (64 KB)
    float* stage  = sm + NN*128;              // STG*8*128 (24 KB)
    float* gate_s = stage + STG*1024;         // SS
    float* rc     = gate_s + SS;              // NN
    int*   sub_s  = (int*)(rc + NN);          // SS
    int*   cnt_s  = sub_s + SS;               // NN
    int b = blockIdx.y, c0 = blockIdx.x*128, tid = threadIdx.x;

    const float* base = lh + (size_t)b*SS*HH + c0;
    int r  = tid >> 5;          // 0..3
    int c4 = (tid & 31)*4;
    // prefetch STG stages of 8 rows each (overlapped with setup below)
    #pragma unroll
    for (int st = 0; st < STG; st++) {
        const float* p = base + (size_t)(st*8)*HH;
        cp16(&stage[st*1024 + r*128 + c4],     p + (size_t)r*HH + c4);
        cp16(&stage[st*1024 + (r+4)*128 + c4], p + (size_t)(r+4)*HH + c4);
        asm volatile("cp.async.commit_group;\n" ::: "memory");
    }

    float4* a4 = (float4*)acc;
    for (int i = tid; i < NN*32; i += 128) a4[i] = make_float4(0.f,0.f,0.f,0.f);
    if (tid < NN) cnt_s[tid] = 0;
    for (int s = tid; s < SS; s += 128) {
        gate_s[s] = g_gate[b*SS + s];
        sub_s[s]  = submap[b*SS + s];
    }
    __syncthreads();
    for (int s = tid; s < SS; s += 128) atomicAdd(&cnt_s[sub_s[s]], 1);

    for (int s0 = 0; s0 < SS; s0 += 8) {
        int st = (s0 >> 3) % STG;
        asm volatile("cp.async.wait_group %0;\n" :: "n"(STG-1) : "memory");
        __syncthreads();
        float v[8];
        #pragma unroll
        for (int j = 0; j < 8; j++) v[j] = stage[st*1024 + j*128 + tid];
        __syncthreads();                     // all reads done before refill
        int sn = s0 + STG*8;
        if (sn < SS) {
            const float* p = base + (size_t)sn*HH;
            cp16(&stage[st*1024 + r*128 + c4],     p + (size_t)r*HH + c4);
            cp16(&stage[st*1024 + (r+4)*128 + c4], p + (size_t)(r+4)*HH + c4);
        }
        asm volatile("cp.async.commit_group;\n" ::: "memory");
        #pragma unroll
        for (int j = 0; j < 8; j++) {
            int n = sub_s[s0+j];
            acc[n*128 + tid] += v[j]*gate_s[s0+j];   // private column: no atomic
        }
    }
    __syncthreads();
    if (tid < NN) rc[tid] = 1.f/fmaxf((float)cnt_s[tid], 1.f);
    __syncthreads();
    for (int n = 0; n < NN; n++)
        g_nf[((size_t)(b*NN + n))*HH + c0 + tid] = acc[n*128 + tid]*rc[n];
}

// ---------------- K3: build dense normalized adjacency (transposed) ---------------
__global__ void k_adj(const int* __restrict__ ei) {
    extern __shared__ float sm[];
    float* cnt = sm;          // NN*NN, [s][d]
    float* deg = sm + NN*NN;  // NN
    int b = blockIdx.x, tid = threadIdx.x;   // 256 threads
    float4* c4 = (float4*)cnt;
    for (int i = tid; i < NN*NN/4; i += 256) c4[i] = make_float4(0.f,0.f,0.f,0.f);
    if (tid < NN) deg[tid] = 1.f;   // self loop
    __syncthreads();
    const int* sP = ei + (size_t)b*2*EE;
    const int* dP = sP + EE;
    for (int e = tid; e < EE; e += 256) {
        int s = sP[e], d = dP[e];
        atomicAdd(&deg[d], 1.f);
        atomicAdd(&cnt[s*NN + d], 1.f);
    }
    __syncthreads();
    if (tid < NN) deg[tid] = rsqrtf(deg[tid]);
    __syncthreads();
    float* outp = g_adjT + (size_t)b*NN*NN;
    for (int i = tid; i < NN*NN; i += 256) {
        int s = i >> 7, d = i & 127;
        float v = cnt[i] + (s == d ? 1.f : 0.f);
        outp[i] = v * deg[d] * deg[s];
    }
}

// ---------------- K4/K6: fp32 GEMM, 32x128 tile (grid 256), FFMA2 ----------------
// C[BNN x 128] = A[BNN x K] @ W[K x 128]; 256 threads, 2x8 per thread
__global__ void __launch_bounds__(256) k_gemm(const float* __restrict__ A,
                                              const float* __restrict__ W,
                                              float* __restrict__ C, int K) {
    __shared__ float As[2][16][34];    // [k][row], pad 34 (conflict-free STS)
    __shared__ float Bs[2][16][128];
    int tid = threadIdx.x;             // 256
    int tx = tid & 15, ty = tid >> 4;  // ty 0..15
    int row0 = blockIdx.x*32;
    int a_r = tid >> 3,  a_k = (tid & 7)*2;   // 32 rows x 16 k via float2
    int b_r = tid >> 5,  b_c = (tid & 31)*4;
    const float* aP  = A + (size_t)(row0 + a_r)*K + a_k;
    const float* bP0 = W + (size_t)b_r*128 + b_c;
    const float* bP1 = W + (size_t)(b_r + 8)*128 + b_c;

    float2 aReg = *(const float2*)aP;
    cp16(&Bs[0][b_r][b_c], bP0);
    cp16(&Bs[0][b_r+8][b_c], bP1);
    asm volatile("cp.async.commit_group;\n" ::: "memory");

    unsigned long long acc[2][4];      // 2 rows x 4 col-pairs
    #pragma unroll
    for (int i = 0; i < 2; i++)
        #pragma unroll
        for (int j = 0; j < 4; j++) acc[i][j] = 0ull;

    int nk = K >> 4;
    for (int kb = 0; kb < nk; kb++) {
        int st = kb & 1;
        As[st][a_k+0][a_r] = aReg.x;
        As[st][a_k+1][a_r] = aReg.y;
        float2 aNext;
        if (kb + 1 < nk) {
            int k0 = (kb + 1) << 4;
            aNext = *(const float2*)(aP + k0);
            cp16(&Bs[st^1][b_r][b_c], bP0 + (size_t)k0*128);
            cp16(&Bs[st^1][b_r+8][b_c], bP1 + (size_t)k0*128);
            asm volatile("cp.async.commit_group;\n" ::: "memory");
            asm volatile("cp.async.wait_group 1;\n" ::: "memory");
        } else {
            asm volatile("cp.async.wait_group 0;\n" ::: "memory");
        }
        __syncthreads();
        #pragma unroll
        for (int kk = 0; kk < 16; kk++) {
            float2 aq = *(const float2*)&As[st][kk][ty*2];           // LDS.64
            ulonglong2 b01 = *(const ulonglong2*)&Bs[st][kk][tx*4];
            ulonglong2 b23 = *(const ulonglong2*)&Bs[st][kk][64 + tx*4];
            unsigned long long a0 = dup2(aq.x), a1 = dup2(aq.y);
            ffma2(acc[0][0], a0, b01.x); ffma2(acc[0][1], a0, b01.y);
            ffma2(acc[0][2], a0, b23.x); ffma2(acc[0][3], a0, b23.y);
            ffma2(acc[1][0], a1, b01.x); ffma2(acc[1][1], a1, b01.y);
            ffma2(acc[1][2], a1, b23.x); ffma2(acc[1][3], a1, b23.y);
        }
        __syncthreads();
        aReg = aNext;
    }
    #pragma unroll
    for (int i = 0; i < 2; i++) {
        float* cr = C + (size_t)(row0 + ty*2 + i)*128;
        float2 p0 = *(float2*)&acc[i][0];
        float2 p1 = *(float2*)&acc[i][1];
        float2 p2 = *(float2*)&acc[i][2];
        float2 p3 = *(float2*)&acc[i][3];
        *(float4*)&cr[tx*4]      = make_float4(p0.x, p0.y, p1.x, p1.y);
        *(float4*)&cr[64 + tx*4] = make_float4(p2.x, p2.y, p3.x, p3.y);
    }
}

// ---------------- K5/K7: GCN aggregation as dense batched GEMM -------------------
// out[d][c] = relu( sum_s AdjT[s][d] * X[s][c] + bias[c] );  grid = BB*2 (c-halves)
template <bool POOL>
__global__ void k_ah(const float* __restrict__ X, const float* __restrict__ bias,
                     float* __restrict__ outp) {
    extern __shared__ float sm[];
    float* At     = sm;                 // NN*NN  (64 KB), [s][d]
    float* Hs     = sm + NN*NN;         // NN*64  (32 KB), [s][c]
    float* red    = Hs + NN*64;         // 16*64
    float* bias_s = red + 16*64;        // 64
    int bx = blockIdx.x;
    int b = bx >> 1, c0 = (bx & 1)*64;
    int tid = threadIdx.x;              // 256
    int tx = tid & 15, ty = tid >> 4;

    const float4* aSrc = (const float4*)(g_adjT + (size_t)b*NN*NN);
    float4* aDst = (float4*)At;
    for (int i = tid; i < NN*NN/4; i += 256) aDst[i] = aSrc[i];
    const float* Xb = X + (size_t)b*NN*GHD + c0;
    for (int i = tid; i < NN*16; i += 256) {
        int s = i >> 4, c = (i & 15)*4;
        *(float4*)&Hs[s*64 + c] = *(const float4*)&Xb[(size_t)s*GHD + c];
    }
    if (tid < 64) bias_s[tid] = bias[c0 + tid];
    __syncthreads();

    unsigned long long acc[8][2];
    #pragma unroll
    for (int r = 0; r < 8; r++) { acc[r][0] = 0ull; acc[r][1] = 0ull; }

    #pragma unroll 4
    for (int s = 0; s < NN; s++) {
        float4 a0 = *(const float4*)&At[s*NN + ty*8];
        float4 a1 = *(const float4*)&At[s*NN + ty*8 + 4];
        ulonglong2 h = *(const ulonglong2*)&Hs[s*64 + tx*4];
        unsigned long long d0 = dup2(a0.x), d1 = dup2(a0.y), d2 = dup2(a0.z), d3 = dup2(a0.w);
        unsigned long long d4 = dup2(a1.x), d5 = dup2(a1.y), d6 = dup2(a1.z), d7 = dup2(a1.w);
        ffma2(acc[0][0], d0, h.x); ffma2(acc[0][1], d0, h.y);
        ffma2(acc[1][0], d1, h.x); ffma2(acc[1][1], d1, h.y);
        ffma2(acc[2][0], d2, h.x); ffma2(acc[2][1], d2, h.y);
        ffma2(acc[3][0], d3, h.x); ffma2(acc[3][1], d3, h.y);
        ffma2(acc[4][0], d4, h.x); ffma2(acc[4][1], d4, h.y);
        ffma2(acc[5][0], d5, h.x); ffma2(acc[5][1], d5, h.y);
        ffma2(acc[6][0], d6, h.x); ffma2(acc[6][1], d6, h.y);
        ffma2(acc[7][0], d7, h.x); ffma2(acc[7][1], d7, h.y);
    }

    float bb0 = bias_s[tx*4+0], bb1 = bias_s[tx*4+1];
    float bb2 = bias_s[tx*4+2], bb3 = bias_s[tx*4+3];
    float ps0 = 0.f, ps1 = 0.f, ps2 = 0.f, ps3 = 0.f;
    #pragma unroll
    for (int r = 0; r < 8; r++) {
        float2 p0 = *(float2*)&acc[r][0];
        float2 p1 = *(float2*)&acc[r][1];
        float v0 = fmaxf(p0.x + bb0, 0.f);
        float v1 = fmaxf(p0.y + bb1, 0.f);
        float v2 = fmaxf(p1.x + bb2, 0.f);
        float v3 = fmaxf(p1.y + bb3, 0.f);
        if (!POOL) {
            int d = ty*8 + r;
            *(float4*)&outp[(size_t)b*NN*GHD + (size_t)d*GHD + c0 + tx*4] =
                make_float4(v0, v1, v2, v3);
        } else {
            ps0 += v0; ps1 += v1; ps2 += v2; ps3 += v3;
        }
    }
    if (POOL) {
        *(float4*)&red[ty*64 + tx*4] = make_float4(ps0, ps1, ps2, ps3);
        __syncthreads();
        if (tid < 64) {
            float ssum = 0.f;
            #pragma unroll
            for (int g = 0; g < 16; g++) ssum += red[g*64 + tid];
            outp[b*GHD + c0 + tid] = ssum * (1.f/NN);
        }
    }
}

// ---------------- K8: final 2-layer MLP ----------------
__global__ void k_fc(const float* __restrict__ lh, const float* __restrict__ Wf1,
                     const float* __restrict__ bf1, const float* __restrict__ Wf2,
                     const float* __restrict__ bf2, float* __restrict__ out) {
    __shared__ float in_s[HH + GHD]; // 896
    __shared__ float hs[FHD];        // 256
    int b = blockIdx.x, tid = threadIdx.x; // 256 threads
    for (int i = tid; i < HH; i += 256) in_s[i] = lh[(size_t)b*SS*HH + i];
    if (tid < GHD) in_s[HH + tid] = g_pool[b*GHD + tid];
    __syncthreads();
    float a = bf1[tid];
    #pragma unroll 8
    for (int k = 0; k < HH + GHD; k++) a += in_s[k]*Wf1[(size_t)k*FHD + tid];
    hs[tid] = fmaxf(a, 0.f);
    __syncthreads();
    if (tid < LL) {
        float o = bf2[tid];
        for (int j = 0; j < FHD; j++) o += hs[j]*Wf2[j*LL + tid];
        out[b*LL + tid] = o;
    }
}

// ---------------- launch ----------------
extern "C" void kernel_launch(void* const* d_in, const int* in_sizes, int n_in,
                              void* d_out, int out_size) {
    const float* lh     = (const float*)d_in[0];
    const int*   submap = (const int*)d_in[1];
    const int*   ei     = (const int*)d_in[2];
    int wbase = (in_sizes[3] == 1) ? 3 : 2;  // num_nodes may be materialized
    const float* wr  = (const float*)d_in[wbase + 1];
    const float* br  = (const float*)d_in[wbase + 2];
    const float* W1  = (const float*)d_in[wbase + 3];
    const float* b1  = (const float*)d_in[wbase + 4];
    const float* W2  = (const float*)d_in[wbase + 5];
    const float* b2  = (const float*)d_in[wbase + 6];
    const float* Wf1 = (const float*)d_in[wbase + 7];
    const float* bf1 = (const float*)d_in[wbase + 8];
    const float* Wf2 = (const float*)d_in[wbase + 9];
    const float* bf2 = (const float*)d_in[wbase + 10];
    float* out = (float*)d_out;

    float *p_nf, *p_x1, *p_h1, *p_x2, *p_pool;
    cudaGetSymbolAddress((void**)&p_nf,   g_nf);
    cudaGetSymbolAddress((void**)&p_x1,   g_x1);
    cudaGetSymbolAddress((void**)&p_h1,   g_h1);
    cudaGetSymbolAddress((void**)&p_x2,   g_x2);
    cudaGetSymbolAddress((void**)&p_pool, g_pool);

    const int smem_seg = (NN*128 + STG*1024 + SS + NN)*sizeof(float)
                       + (SS + NN)*sizeof(int);                                     // ~95 KB
    const int smem_adj = (NN*NN + NN)*sizeof(float);                                // ~66 KB
    const int smem_ah  = (NN*NN + NN*64 + 16*64 + 64)*sizeof(float);                // ~100.5 KB
    cudaFuncSetAttribute(k_segsum,    cudaFuncAttributeMaxDynamicSharedMemorySize, smem_seg);
    cudaFuncSetAttribute(k_adj,       cudaFuncAttributeMaxDynamicSharedMemorySize, smem_adj);
    cudaFuncSetAttribute(k_ah<false>, cudaFuncAttributeMaxDynamicSharedMemorySize, smem_ah);
    cudaFuncSetAttribute(k_ah<true>,  cudaFuncAttributeMaxDynamicSharedMemorySize, smem_ah);

    k_gate<<<(BB*SS*32)/256, 256>>>(lh, wr, br);
    k_segsum<<<dim3(6, BB), 128, smem_seg>>>(lh, submap);
    k_adj<<<BB, 256, smem_adj>>>(ei);
    k_gemm<<<BNN/32, 256>>>(p_nf, W1, p_x1, HH);
    k_ah<false><<<BB*2, 256, smem_ah>>>(p_x1, b1, p_h1);
    k_gemm<<<BNN/32, 256>>>(p_h1, W2, p_x2, GHD);
    k_ah<true><<<BB*2, 256, smem_ah>>>(p_x2, b2, p_pool);
    k_fc<<<BB, 256>>>(lh, Wf1, bf1, Wf2, bf2, out);
}

// round 9
// speedup vs baseline: 2.5251x; 1.1900x over previous
#include <cuda_runtime.h>
#include <math.h>

// Problem constants
#define BB  64
#define SS  512
#define HH  768
#define NN  128
#define EE  1024
#define GHD 128
#define FHD 256
#define LL  2
#define BNN (BB*NN)   // 8192
#define STG 6         // segsum pipeline depth

// ---------------- scratch (device globals; no allocation allowed) ----------------
__device__ float g_gate[BB*SS];
__device__ float g_nf[(size_t)BNN*HH];        // 25 MB
__device__ float g_adjT[(size_t)BB*NN*NN];    // 4 MB, [b][s][d]
__device__ float g_x1a[(size_t)BNN*GHD];
__device__ float g_x1b[(size_t)BNN*GHD];
__device__ float g_h1[(size_t)BNN*GHD];
__device__ float g_x2[(size_t)BNN*GHD];
__device__ float g_pool[BB*GHD];

// ---------------- helpers ----------------
__device__ __forceinline__ void cp16(void* smem, const void* g) {
    unsigned a = (unsigned)__cvta_generic_to_shared(smem);
    asm volatile("cp.async.cg.shared.global [%0], [%1], 16;\n" :: "r"(a), "l"(g));
}
__device__ __forceinline__ unsigned long long dup2(float a) {
    unsigned long long r;
    asm("mov.b64 %0, {%1, %1};" : "=l"(r) : "f"(a));
    return r;
}
__device__ __forceinline__ void ffma2(unsigned long long& d, unsigned long long a,
                                      unsigned long long b) {
    asm("fma.rn.f32x2 %0, %1, %2, %0;" : "+l"(d) : "l"(a), "l"(b));
}

// ---------------- K1: gate = sigmoid(lh . wr + br) ----------------
__global__ void k_gate(const float* __restrict__ lh,
                       const float* __restrict__ wr, const float* __restrict__ brp) {
    int warp = (blockIdx.x*blockDim.x + threadIdx.x) >> 5;
    int lane = threadIdx.x & 31;
    if (warp >= BB*SS) return;
    const float4* row4 = (const float4*)(lh + (size_t)warp*HH);
    const float4* w4   = (const float4*)wr;
    float dot = 0.f;
    #pragma unroll
    for (int i = 0; i < 6; i++) {
        float4 a = row4[lane + 32*i];
        float4 w = w4[lane + 32*i];
        dot += a.x*w.x + a.y*w.y + a.z*w.z + a.w*w.w;
    }
    #pragma unroll
    for (int off = 16; off; off >>= 1) dot += __shfl_xor_sync(0xffffffffu, dot, off);
    if (lane == 0)
        g_gate[warp] = 1.f/(1.f + expf(-(dot + brp[0])));
}

// ---------------- K2: segment mean — cp.async streaming, thread-private columns ---
// grid (6, 64), 128 threads; CTA = (batch b, 128-dim chunk c0)
__global__ void k_segsum(const float* __restrict__ lh, const int* __restrict__ submap) {
    extern __shared__ float sm[];
    float* acc    = sm;                       // NN*128 (64 KB)
    float* stage  = sm + NN*128;              // STG*8*128 (24 KB)
    float* gate_s = stage + STG*1024;         // SS
    float* rc     = gate_s + SS;              // NN
    int*   sub_s  = (int*)(rc + NN);          // SS
    int*   cnt_s  = sub_s + SS;               // NN
    int b = blockIdx.y, c0 = blockIdx.x*128, tid = threadIdx.x;

    const float* base = lh + (size_t)b*SS*HH + c0;
    int r  = tid >> 5;          // 0..3
    int c4 = (tid & 31)*4;
    #pragma unroll
    for (int st = 0; st < STG; st++) {
        const float* p = base + (size_t)(st*8)*HH;
        cp16(&stage[st*1024 + r*128 + c4],     p + (size_t)r*HH + c4);
        cp16(&stage[st*1024 + (r+4)*128 + c4], p + (size_t)(r+4)*HH + c4);
        asm volatile("cp.async.commit_group;\n" ::: "memory");
    }

    float4* a4 = (float4*)acc;
    for (int i = tid; i < NN*32; i += 128) a4[i] = make_float4(0.f,0.f,0.f,0.f);
    if (tid < NN) cnt_s[tid] = 0;
    for (int s = tid; s < SS; s += 128) {
        gate_s[s] = g_gate[b*SS + s];
        sub_s[s]  = submap[b*SS + s];
    }
    __syncthreads();
    for (int s = tid; s < SS; s += 128) atomicAdd(&cnt_s[sub_s[s]], 1);

    for (int s0 = 0; s0 < SS; s0 += 8) {
        int st = (s0 >> 3) % STG;
        asm volatile("cp.async.wait_group %0;\n" :: "n"(STG-1) : "memory");
        __syncthreads();
        float v[8];
        #pragma unroll
        for (int j = 0; j < 8; j++) v[j] = stage[st*1024 + j*128 + tid];
        __syncthreads();                     // all reads done before refill
        int sn = s0 + STG*8;
        if (sn < SS) {
            const float* p = base + (size_t)sn*HH;
            cp16(&stage[st*1024 + r*128 + c4],     p + (size_t)r*HH + c4);
            cp16(&stage[st*1024 + (r+4)*128 + c4], p + (size_t)(r+4)*HH + c4);
        }
        asm volatile("cp.async.commit_group;\n" ::: "memory");
        #pragma unroll
        for (int j = 0; j < 8; j++) {
            int n = sub_s[s0+j];
            acc[n*128 + tid] += v[j]*gate_s[s0+j];   // private column: no atomic
        }
    }
    __syncthreads();
    if (tid < NN) rc[tid] = 1.f/fmaxf((float)cnt_s[tid], 1.f);
    __syncthreads();
    for (int n = 0; n < NN; n++)
        g_nf[((size_t)(b*NN + n))*HH + c0 + tid] = acc[n*128 + tid]*rc[n];
}

// ---------------- K3: build dense normalized adjacency (transposed) ---------------
__global__ void k_adj(const int* __restrict__ ei) {
    extern __shared__ float sm[];
    float* cnt = sm;          // NN*NN, [s][d]
    float* deg = sm + NN*NN;  // NN
    int b = blockIdx.x, tid = threadIdx.x;   // 256 threads
    float4* c4 = (float4*)cnt;
    for (int i = tid; i < NN*NN/4; i += 256) c4[i] = make_float4(0.f,0.f,0.f,0.f);
    if (tid < NN) deg[tid] = 1.f;   // self loop
    __syncthreads();
    const int* sP = ei + (size_t)b*2*EE;
    const int* dP = sP + EE;
    for (int e = tid; e < EE; e += 256) {
        int s = sP[e], d = dP[e];
        atomicAdd(&deg[d], 1.f);
        atomicAdd(&cnt[s*NN + d], 1.f);
    }
    __syncthreads();
    if (tid < NN) deg[tid] = rsqrtf(deg[tid]);
    __syncthreads();
    float* outp = g_adjT + (size_t)b*NN*NN;
    for (int i = tid; i < NN*NN; i += 256) {
        int s = i >> 7, d = i & 127;
        float v = cnt[i] + (s == d ? 1.f : 0.f);
        outp[i] = v * deg[d] * deg[s];
    }
}

// ---------------- K4/K6: fp32 GEMM, 32x128 tile, 128 threads, 4x8, FFMA2 ----------
// C = A[:, k0:k0+KC] @ W[k0:k0+KC, :]; blockIdx.y selects K-half + output buffer
__global__ void __launch_bounds__(128) k_gemm(const float* __restrict__ A,
                                              const float* __restrict__ W,
                                              float* __restrict__ Ca,
                                              float* __restrict__ Cb,
                                              int K, int KC) {
    __shared__ float As[2][16][36];    // [k][row], pitch 36 (16B-aligned rows)
    __shared__ float Bs[2][16][128];
    int tid = threadIdx.x;             // 128
    int tx = tid & 15, ty = tid >> 4;  // ty 0..7
    int row0 = blockIdx.x*32;
    int k0 = blockIdx.y * KC;
    float* C = blockIdx.y ? Cb : Ca;
    int a_r = tid >> 2,  a_k = (tid & 3)*4;   // 32 rows x 16 k via float4
    int b_r = tid >> 5,  b_c = (tid & 31)*4;  // 4 rows per thread (+0,4,8,12)
    const float* aP = A + (size_t)(row0 + a_r)*K + k0 + a_k;
    const float* bP = W + (size_t)(k0 + b_r)*128 + b_c;

    float4 aReg = *(const float4*)aP;
    #pragma unroll
    for (int rr = 0; rr < 4; rr++)
        cp16(&Bs[0][b_r + 4*rr][b_c], bP + (size_t)(4*rr)*128);
    asm volatile("cp.async.commit_group;\n" ::: "memory");

    unsigned long long acc[4][4];      // 4 rows x 4 col-pairs (f32x2)
    #pragma unroll
    for (int i = 0; i < 4; i++)
        #pragma unroll
        for (int j = 0; j < 4; j++) acc[i][j] = 0ull;

    int nk = KC >> 4;
    for (int kb = 0; kb < nk; kb++) {
        int st = kb & 1;
        As[st][a_k+0][a_r] = aReg.x;
        As[st][a_k+1][a_r] = aReg.y;
        As[st][a_k+2][a_r] = aReg.z;
        As[st][a_k+3][a_r] = aReg.w;
        float4 aNext;
        if (kb + 1 < nk) {
            int kn = (kb + 1) << 4;
            aNext = *(const float4*)(aP + kn);
            #pragma unroll
            for (int rr = 0; rr < 4; rr++)
                cp16(&Bs[st^1][b_r + 4*rr][b_c], bP + (size_t)(kn + 4*rr)*128);
            asm volatile("cp.async.commit_group;\n" ::: "memory");
            asm volatile("cp.async.wait_group 1;\n" ::: "memory");
        } else {
            asm volatile("cp.async.wait_group 0;\n" ::: "memory");
        }
        __syncthreads();
        #pragma unroll
        for (int kk = 0; kk < 16; kk++) {
            float4 aq = *(const float4*)&As[st][kk][ty*4];           // LDS.128
            ulonglong2 b01 = *(const ulonglong2*)&Bs[st][kk][tx*4];
            ulonglong2 b23 = *(const ulonglong2*)&Bs[st][kk][64 + tx*4];
            unsigned long long a0 = dup2(aq.x), a1 = dup2(aq.y);
            unsigned long long a2 = dup2(aq.z), a3 = dup2(aq.w);
            ffma2(acc[0][0], a0, b01.x); ffma2(acc[0][1], a0, b01.y);
            ffma2(acc[0][2], a0, b23.x); ffma2(acc[0][3], a0, b23.y);
            ffma2(acc[1][0], a1, b01.x); ffma2(acc[1][1], a1, b01.y);
            ffma2(acc[1][2], a1, b23.x); ffma2(acc[1][3], a1, b23.y);
            ffma2(acc[2][0], a2, b01.x); ffma2(acc[2][1], a2, b01.y);
            ffma2(acc[2][2], a2, b23.x); ffma2(acc[2][3], a2, b23.y);
            ffma2(acc[3][0], a3, b01.x); ffma2(acc[3][1], a3, b01.y);
            ffma2(acc[3][2], a3, b23.x); ffma2(acc[3][3], a3, b23.y);
        }
        __syncthreads();
        aReg = aNext;
    }
    #pragma unroll
    for (int i = 0; i < 4; i++) {
        float* cr = C + (size_t)(row0 + ty*4 + i)*128;
        float2 p0 = *(float2*)&acc[i][0];
        float2 p1 = *(float2*)&acc[i][1];
        float2 p2 = *(float2*)&acc[i][2];
        float2 p3 = *(float2*)&acc[i][3];
        *(float4*)&cr[tx*4]      = make_float4(p0.x, p0.y, p1.x, p1.y);
        *(float4*)&cr[64 + tx*4] = make_float4(p2.x, p2.y, p3.x, p3.y);
    }
}

// ---------------- K5/K7: GCN aggregation as dense batched GEMM -------------------
// out[d][c] = relu( sum_s AdjT[s][d]*(Xa+Xb)[s][c] + bias[c] );  grid = BB*2
template <bool POOL>
__global__ void k_ah(const float* __restrict__ Xa, const float* __restrict__ Xb,
                     const float* __restrict__ bias, float* __restrict__ outp) {
    extern __shared__ float sm[];
    float* At     = sm;                 // NN*NN  (64 KB), [s][d]
    float* Hs     = sm + NN*NN;         // NN*64  (32 KB), [s][c]
    float* red    = Hs + NN*64;         // 32*64  (8 KB, POOL reduce)
    float* bias_s = red + 32*64;        // 64
    int bx = blockIdx.x;
    int b = bx >> 1, c0 = (bx & 1)*64;
    int tid = threadIdx.x;              // 256
    int tx = tid & 7;                   // cols c = tx*8 .. +7
    int ty = tid >> 3;                  // rows d = ty*4 .. +3

    const float4* aSrc = (const float4*)(g_adjT + (size_t)b*NN*NN);
    float4* aDst = (float4*)At;
    for (int i = tid; i < NN*NN/4; i += 256) aDst[i] = aSrc[i];
    const float* XaB = Xa + (size_t)b*NN*GHD + c0;
    const float* XbB = Xb ? Xb + (size_t)b*NN*GHD + c0 : (const float*)0;
    for (int i = tid; i < NN*16; i += 256) {
        int s = i >> 4, c = (i & 15)*4;
        float4 v = *(const float4*)&XaB[(size_t)s*GHD + c];
        if (XbB) {
            float4 w = *(const float4*)&XbB[(size_t)s*GHD + c];
            v.x += w.x; v.y += w.y; v.z += w.z; v.w += w.w;
        }
        *(float4*)&Hs[s*64 + c] = v;
    }
    if (tid < 64) bias_s[tid] = bias[c0 + tid];
    __syncthreads();

    unsigned long long acc[4][4];       // [row i][col pair]
    #pragma unroll
    for (int i = 0; i < 4; i++)
        #pragma unroll
        for (int j = 0; j < 4; j++) acc[i][j] = 0ull;

    #pragma unroll 4
    for (int s = 0; s < NN; s++) {
        float4 av = *(const float4*)&At[s*NN + ty*4];
        ulonglong2 h0 = *(const ulonglong2*)&Hs[s*64 + tx*8];
        ulonglong2 h1 = *(const ulonglong2*)&Hs[s*64 + tx*8 + 4];
        unsigned long long d0 = dup2(av.x), d1 = dup2(av.y);
        unsigned long long d2 = dup2(av.z), d3 = dup2(av.w);
        ffma2(acc[0][0], d0, h0.x); ffma2(acc[0][1], d0, h0.y);
        ffma2(acc[0][2], d0, h1.x); ffma2(acc[0][3], d0, h1.y);
        ffma2(acc[1][0], d1, h0.x); ffma2(acc[1][1], d1, h0.y);
        ffma2(acc[1][2], d1, h1.x); ffma2(acc[1][3], d1, h1.y);
        ffma2(acc[2][0], d2, h0.x); ffma2(acc[2][1], d2, h0.y);
        ffma2(acc[2][2], d2, h1.x); ffma2(acc[2][3], d2, h1.y);
        ffma2(acc[3][0], d3, h0.x); ffma2(acc[3][1], d3, h0.y);
        ffma2(acc[3][2], d3, h1.x); ffma2(acc[3][3], d3, h1.y);
    }

    float bb[8];
    #pragma unroll
    for (int j = 0; j < 8; j++) bb[j] = bias_s[tx*8 + j];
    float ps[8];
    #pragma unroll
    for (int j = 0; j < 8; j++) ps[j] = 0.f;
    #pragma unroll
    for (int i = 0; i < 4; i++) {
        float v[8];
        #pragma unroll
        for (int p = 0; p < 4; p++) {
            float2 pr = *(float2*)&acc[i][p];
            v[2*p]   = fmaxf(pr.x + bb[2*p],   0.f);
            v[2*p+1] = fmaxf(pr.y + bb[2*p+1], 0.f);
        }
        if (!POOL) {
            int d = ty*4 + i;
            float* orow = outp + (size_t)b*NN*GHD + (size_t)d*GHD + c0 + tx*8;
            *(float4*)orow       = make_float4(v[0], v[1], v[2], v[3]);
            *(float4*)(orow + 4) = make_float4(v[4], v[5], v[6], v[7]);
        } else {
            #pragma unroll
            for (int j = 0; j < 8; j++) ps[j] += v[j];
        }
    }
    if (POOL) {
        *(float4*)&red[ty*64 + tx*8]     = make_float4(ps[0], ps[1], ps[2], ps[3]);
        *(float4*)&red[ty*64 + tx*8 + 4] = make_float4(ps[4], ps[5], ps[6], ps[7]);
        __syncthreads();
        if (tid < 64) {
            float ssum = 0.f;
            #pragma unroll
            for (int g = 0; g < 32; g++) ssum += red[g*64 + tid];
            outp[b*GHD + c0 + tid] = ssum * (1.f/NN);
        }
    }
}

// ---------------- K8: final 2-layer MLP (multi-accumulator ILP) ----------------
__global__ void k_fc(const float* __restrict__ lh, const float* __restrict__ Wf1,
                     const float* __restrict__ bf1, const float* __restrict__ Wf2,
                     const float* __restrict__ bf2, float* __restrict__ out) {
    __shared__ float in_s[HH + GHD]; // 896
    __shared__ float hs[FHD];        // 256
    int b = blockIdx.x, tid = threadIdx.x; // 256 threads
    for (int i = tid; i < HH; i += 256) in_s[i] = lh[(size_t)b*SS*HH + i];
    if (tid < GHD) in_s[HH + tid] = g_pool[b*GHD + tid];
    __syncthreads();
    float a0 = 0.f, a1 = 0.f, a2 = 0.f, a3 = 0.f;
    #pragma unroll 8
    for (int k = 0; k < HH + GHD; k += 4) {
        a0 += in_s[k+0]*Wf1[(size_t)(k+0)*FHD + tid];
        a1 += in_s[k+1]*Wf1[(size_t)(k+1)*FHD + tid];
        a2 += in_s[k+2]*Wf1[(size_t)(k+2)*FHD + tid];
        a3 += in_s[k+3]*Wf1[(size_t)(k+3)*FHD + tid];
    }
    hs[tid] = fmaxf(bf1[tid] + (a0 + a1) + (a2 + a3), 0.f);
    __syncthreads();
    if (tid < LL) {
        float o = bf2[tid];
        for (int j = 0; j < FHD; j++) o += hs[j]*Wf2[j*LL + tid];
        out[b*LL + tid] = o;
    }
}

// ---------------- launch ----------------
extern "C" void kernel_launch(void* const* d_in, const int* in_sizes, int n_in,
                              void* d_out, int out_size) {
    const float* lh     = (const float*)d_in[0];
    const int*   submap = (const int*)d_in[1];
    const int*   ei     = (const int*)d_in[2];
    int wbase = (in_sizes[3] == 1) ? 3 : 2;  // num_nodes may be materialized
    const float* wr  = (const float*)d_in[wbase + 1];
    const float* br  = (const float*)d_in[wbase + 2];
    const float* W1  = (const float*)d_in[wbase + 3];
    const float* b1  = (const float*)d_in[wbase + 4];
    const float* W2  = (const float*)d_in[wbase + 5];
    const float* b2  = (const float*)d_in[wbase + 6];
    const float* Wf1 = (const float*)d_in[wbase + 7];
    const float* bf1 = (const float*)d_in[wbase + 8];
    const float* Wf2 = (const float*)d_in[wbase + 9];
    const float* bf2 = (const float*)d_in[wbase + 10];
    float* out = (float*)d_out;

    float *p_nf, *p_x1a, *p_x1b, *p_h1, *p_x2, *p_pool;
    cudaGetSymbolAddress((void**)&p_nf,   g_nf);
    cudaGetSymbolAddress((void**)&p_x1a,  g_x1a);
    cudaGetSymbolAddress((void**)&p_x1b,  g_x1b);
    cudaGetSymbolAddress((void**)&p_h1,   g_h1);
    cudaGetSymbolAddress((void**)&p_x2,   g_x2);
    cudaGetSymbolAddress((void**)&p_pool, g_pool);

    const int smem_seg = (NN*128 + STG*1024 + SS + NN)*sizeof(float)
                       + (SS + NN)*sizeof(int);                                     // ~95 KB
    const int smem_adj = (NN*NN + NN)*sizeof(float);                                // ~66 KB
    const int smem_ah  = (NN*NN + NN*64 + 32*64 + 64)*sizeof(float);                // ~104.5 KB
    cudaFuncSetAttribute(k_segsum,    cudaFuncAttributeMaxDynamicSharedMemorySize, smem_seg);
    cudaFuncSetAttribute(k_adj,       cudaFuncAttributeMaxDynamicSharedMemorySize, smem_adj);
    cudaFuncSetAttribute(k_ah<false>, cudaFuncAttributeMaxDynamicSharedMemorySize, smem_ah);
    cudaFuncSetAttribute(k_ah<true>,  cudaFuncAttributeMaxDynamicSharedMemorySize, smem_ah);

    k_gate<<<(BB*SS*32)/256, 256>>>(lh, wr, br);
    k_segsum<<<dim3(6, BB), 128, smem_seg>>>(lh, submap);
    k_adj<<<BB, 256, smem_adj>>>(ei);
    // GEMM1: K=768 split into two 384-halves (y-dim), disjoint outputs
    k_gemm<<<dim3(BNN/32, 2), 128>>>(p_nf, W1, p_x1a, p_x1b, HH, HH/2);
    k_ah<false><<<BB*2, 256, smem_ah>>>(p_x1a, p_x1b, b1, p_h1);
    // GEMM2: K=128, no split
    k_gemm<<<dim3(BNN/32, 1), 128>>>(p_h1, W2, p_x2, p_x2, GHD, GHD);
    k_ah<true><<<BB*2, 256, smem_ah>>>(p_x2, (const float*)0, b2, p_pool);
    k_fc<<<BB, 256>>>(lh, Wf1, bf1, Wf2, bf2, out);
}

// round 11
// speedup vs baseline: 2.6846x; 1.0632x over previous
#include <cuda_runtime.h>
#include <math.h>
#include <stdint.h>

// Problem constants
#define BB  64
#define SS  512
#define HH  768
#define NN  128
#define EE  1024
#define GHD 128
#define FHD 256
#define LL  2
#define BNN (BB*NN)   // 8192
#define STG 6         // segsum pipeline depth
#define APITCH 20     // As row pitch (floats) - conflict-free
#define BPITCH 136    // Bs row pitch (floats) - conflict-free

// ---------------- scratch (device globals; no allocation allowed) ----------------
__device__ float g_gate[BB*SS];
__device__ float g_nf[(size_t)BNN*HH];        // 25 MB (tf32-rounded)
__device__ float g_adjT[(size_t)BB*NN*NN];    // 4 MB, [b][s][d]
__device__ float g_wr1[(size_t)HH*GHD];       // W1 tf32-rounded [768][128]
__device__ float g_wr2[(size_t)GHD*GHD];      // W2 tf32-rounded [128][128]
__device__ float g_x1[(size_t)BNN*GHD];
__device__ float g_h1[(size_t)BNN*GHD];       // tf32-rounded
__device__ float g_x2[(size_t)BNN*GHD];
__device__ float g_pool[BB*GHD];

// ---------------- helpers ----------------
__device__ __forceinline__ void cp16(void* smem, const void* g) {
    unsigned a = (unsigned)__cvta_generic_to_shared(smem);
    asm volatile("cp.async.cg.shared.global [%0], [%1], 16;\n" :: "r"(a), "l"(g));
}
__device__ __forceinline__ unsigned long long dup2(float a) {
    unsigned long long r;
    asm("mov.b64 %0, {%1, %1};" : "=l"(r) : "f"(a));
    return r;
}
__device__ __forceinline__ void ffma2(unsigned long long& d, unsigned long long a,
                                      unsigned long long b) {
    asm("fma.rn.f32x2 %0, %1, %2, %0;" : "+l"(d) : "l"(a), "l"(b));
}
__device__ __forceinline__ float tf32r(float x) {
    uint32_t o;
    asm("cvt.rna.tf32.f32 %0, %1;" : "=r"(o) : "f"(x));
    return __uint_as_float(o);
}
__device__ __forceinline__ void mma_tf32(float* c, const uint32_t* a,
                                         uint32_t b0, uint32_t b1) {
    asm volatile(
        "mma.sync.aligned.m16n8k8.row.col.f32.tf32.tf32.f32 "
        "{%0,%1,%2,%3}, {%4,%5,%6,%7}, {%8,%9}, {%0,%1,%2,%3};"
        : "+f"(c[0]), "+f"(c[1]), "+f"(c[2]), "+f"(c[3])
        : "r"(a[0]), "r"(a[1]), "r"(a[2]), "r"(a[3]), "r"(b0), "r"(b1));
}

// ---------------- K1: gate = sigmoid(lh . wr + br) ----------------
__global__ void k_gate(const float* __restrict__ lh,
                       const float* __restrict__ wr, const float* __restrict__ brp) {
    int warp = (blockIdx.x*blockDim.x + threadIdx.x) >> 5;
    int lane = threadIdx.x & 31;
    if (warp >= BB*SS) return;
    const float4* row4 = (const float4*)(lh + (size_t)warp*HH);
    const float4* w4   = (const float4*)wr;
    float dot = 0.f;
    #pragma unroll
    for (int i = 0; i < 6; i++) {
        float4 a = row4[lane + 32*i];
        float4 w = w4[lane + 32*i];
        dot += a.x*w.x + a.y*w.y + a.z*w.z + a.w*w.w;
    }
    #pragma unroll
    for (int off = 16; off; off >>= 1) dot += __shfl_xor_sync(0xffffffffu, dot, off);
    if (lane == 0)
        g_gate[warp] = 1.f/(1.f + expf(-(dot + brp[0])));
}

// ---------------- K2: segment mean — cp.async streaming, thread-private columns ---
__global__ void k_segsum(const float* __restrict__ lh, const int* __restrict__ submap) {
    extern __shared__ float sm[];
    float* acc    = sm;                       // NN*128 (64 KB)
    float* stage  = sm + NN*128;              // STG*8*128 (24 KB)
    float* gate_s = stage + STG*1024;         // SS
    float* rc     = gate_s + SS;              // NN
    int*   sub_s  = (int*)(rc + NN);          // SS
    int*   cnt_s  = sub_s + SS;               // NN
    int b = blockIdx.y, c0 = blockIdx.x*128, tid = threadIdx.x;

    const float* base = lh + (size_t)b*SS*HH + c0;
    int r  = tid >> 5;          // 0..3
    int c4 = (tid & 31)*4;
    #pragma unroll
    for (int st = 0; st < STG; st++) {
        const float* p = base + (size_t)(st*8)*HH;
        cp16(&stage[st*1024 + r*128 + c4],     p + (size_t)r*HH + c4);
        cp16(&stage[st*1024 + (r+4)*128 + c4], p + (size_t)(r+4)*HH + c4);
        asm volatile("cp.async.commit_group;\n" ::: "memory");
    }

    float4* a4 = (float4*)acc;
    for (int i = tid; i < NN*32; i += 128) a4[i] = make_float4(0.f,0.f,0.f,0.f);
    if (tid < NN) cnt_s[tid] = 0;
    for (int s = tid; s < SS; s += 128) {
        gate_s[s] = g_gate[b*SS + s];
        sub_s[s]  = submap[b*SS + s];
    }
    __syncthreads();
    for (int s = tid; s < SS; s += 128) atomicAdd(&cnt_s[sub_s[s]], 1);

    for (int s0 = 0; s0 < SS; s0 += 8) {
        int st = (s0 >> 3) % STG;
        asm volatile("cp.async.wait_group %0;\n" :: "n"(STG-1) : "memory");
        __syncthreads();
        float v[8];
        #pragma unroll
        for (int j = 0; j < 8; j++) v[j] = stage[st*1024 + j*128 + tid];
        __syncthreads();
        int sn = s0 + STG*8;
        if (sn < SS) {
            const float* p = base + (size_t)sn*HH;
            cp16(&stage[st*1024 + r*128 + c4],     p + (size_t)r*HH + c4);
            cp16(&stage[st*1024 + (r+4)*128 + c4], p + (size_t)(r+4)*HH + c4);
        }
        asm volatile("cp.async.commit_group;\n" ::: "memory");
        #pragma unroll
        for (int j = 0; j < 8; j++) {
            int n = sub_s[s0+j];
            acc[n*128 + tid] += v[j]*gate_s[s0+j];
        }
    }
    __syncthreads();
    if (tid < NN) rc[tid] = 1.f/fmaxf((float)cnt_s[tid], 1.f);
    __syncthreads();
    // tf32 pre-round: feeds the tf32 MMA GEMM1 directly
    for (int n = 0; n < NN; n++)
        g_nf[((size_t)(b*NN + n))*HH + c0 + tid] = tf32r(acc[n*128 + tid]*rc[n]);
}

// ---------------- K3: build dense normalized adjacency (transposed) ---------------
__global__ void k_adj(const int* __restrict__ ei) {
    extern __shared__ float sm[];
    float* cnt = sm;          // NN*NN, [s][d]
    float* deg = sm + NN*NN;  // NN
    int b = blockIdx.x, tid = threadIdx.x;   // 256 threads
    float4* c4 = (float4*)cnt;
    for (int i = tid; i < NN*NN/4; i += 256) c4[i] = make_float4(0.f,0.f,0.f,0.f);
    if (tid < NN) deg[tid] = 1.f;   // self loop
    __syncthreads();
    const int* sP = ei + (size_t)b*2*EE;
    const int* dP = sP + EE;
    for (int e = tid; e < EE; e += 256) {
        int s = sP[e], d = dP[e];
        atomicAdd(&deg[d], 1.f);
        atomicAdd(&cnt[s*NN + d], 1.f);
    }
    __syncthreads();
    if (tid < NN) deg[tid] = rsqrtf(deg[tid]);
    __syncthreads();
    float* outp = g_adjT + (size_t)b*NN*NN;
    for (int i = tid; i < NN*NN; i += 256) {
        int s = i >> 7, d = i & 127;
        float v = cnt[i] + (s == d ? 1.f : 0.f);
        outp[i] = v * deg[d] * deg[s];
    }
}

// ---------------- K3b: tf32-round W1, W2 ----------------
__global__ void k_round(const float* __restrict__ W1, const float* __restrict__ W2,
                        float* __restrict__ R1, float* __restrict__ R2) {
    int i = blockIdx.x*256 + threadIdx.x;
    if (i < HH*GHD)  R1[i] = tf32r(W1[i]);
    if (i < GHD*GHD) R2[i] = tf32r(W2[i]);
}

// ---------------- K4/K6: tf32 mma.sync GEMM  C[BNN x 128] = A[BNN x K] @ W[K x 128]
// 64x128 tile, 128 threads (4 warps: 2m x 2n), warp = 32 rows x 64 cols.
// m16n8k8.row.col: B col-major fragment = W[k][n] natural layout.
__global__ void __launch_bounds__(128) k_mma(const float* __restrict__ A,
                                             const float* __restrict__ B,
                                             float* __restrict__ C, int K) {
    __shared__ float As[2][64][APITCH];    // 10240 B
    __shared__ float Bs[2][16][BPITCH];    // 17408 B
    int tid = threadIdx.x, lane = tid & 31, wid = tid >> 5;
    int wm = wid & 1, wn = wid >> 1;
    int row0 = blockIdx.x*64;
    int r = lane >> 2, c = lane & 3;

    auto loadStage = [&](int st, int k0) {
        #pragma unroll
        for (int q = 0; q < 2; q++) {
            int idx = tid*2 + q;           // 256 chunks: 64 rows x 4 k4
            int row = idx >> 2, k4 = (idx & 3)*4;
            cp16(&As[st][row][k4], A + (size_t)(row0 + row)*K + k0 + k4);
        }
        #pragma unroll
        for (int q = 0; q < 4; q++) {
            int idx = tid*4 + q;           // 512 chunks: 16 rows x 32 c4
            int row = idx >> 5, cc = (idx & 31)*4;
            cp16(&Bs[st][row][cc], B + (size_t)(k0 + row)*GHD + cc);
        }
        asm volatile("cp.async.commit_group;\n" ::: "memory");
    };
    loadStage(0, 0);

    float acc[2][8][4];
    #pragma unroll
    for (int t = 0; t < 2; t++)
        #pragma unroll
        for (int j = 0; j < 8; j++)
            #pragma unroll
            for (int q = 0; q < 4; q++) acc[t][j][q] = 0.f;

    int nk = K >> 4;
    for (int kb = 0; kb < nk; kb++) {
        int st = kb & 1;
        if (kb + 1 < nk) {
            loadStage(st^1, (kb + 1) << 4);
            asm volatile("cp.async.wait_group 1;\n" ::: "memory");
        } else {
            asm volatile("cp.async.wait_group 0;\n" ::: "memory");
        }
        __syncthreads();
        #pragma unroll
        for (int ks = 0; ks < 16; ks += 8) {
            uint32_t a[2][4];
            #pragma unroll
            for (int t = 0; t < 2; t++) {
                int rr = wm*32 + t*16 + r;
                a[t][0] = __float_as_uint(As[st][rr    ][ks + c]);
                a[t][1] = __float_as_uint(As[st][rr + 8][ks + c]);
                a[t][2] = __float_as_uint(As[st][rr    ][ks + c + 4]);
                a[t][3] = __float_as_uint(As[st][rr + 8][ks + c + 4]);
            }
            #pragma unroll
            for (int j = 0; j < 8; j++) {
                int nc = wn*64 + j*8 + r;
                uint32_t b0 = __float_as_uint(Bs[st][ks + c    ][nc]);
                uint32_t b1 = __float_as_uint(Bs[st][ks + c + 4][nc]);
                mma_tf32(acc[0][j], a[0], b0, b1);
                mma_tf32(acc[1][j], a[1], b0, b1);
            }
        }
        __syncthreads();
    }
    #pragma unroll
    for (int t = 0; t < 2; t++) {
        int rr = row0 + wm*32 + t*16 + r;
        #pragma unroll
        for (int j = 0; j < 8; j++) {
            int cc = wn*64 + j*8 + 2*c;
            *(float2*)&C[(size_t)rr*GHD + cc]       = make_float2(acc[t][j][0], acc[t][j][1]);
            *(float2*)&C[(size_t)(rr + 8)*GHD + cc] = make_float2(acc[t][j][2], acc[t][j][3]);
        }
    }
}

// ---------------- K5/K7: GCN aggregation as dense batched GEMM -------------------
template <bool POOL>
__global__ void k_ah(const float* __restrict__ Xa, const float* __restrict__ Xb,
                     const float* __restrict__ bias, float* __restrict__ outp) {
    extern __shared__ float sm[];
    float* At     = sm;                 // NN*NN  (64 KB), [s][d]
    float* Hs     = sm + NN*NN;         // NN*64  (32 KB), [s][c]
    float* red    = Hs + NN*64;         // 32*64
    float* bias_s = red + 32*64;        // 64
    int bx = blockIdx.x;
    int b = bx >> 1, c0 = (bx & 1)*64;
    int tid = threadIdx.x;              // 256
    int tx = tid & 7;                   // cols c = tx*8 .. +7
    int ty = tid >> 3;                  // rows d = ty*4 .. +3

    const float4* aSrc = (const float4*)(g_adjT + (size_t)b*NN*NN);
    float4* aDst = (float4*)At;
    for (int i = tid; i < NN*NN/4; i += 256) aDst[i] = aSrc[i];
    const float* XaB = Xa + (size_t)b*NN*GHD + c0;
    const float* XbB = Xb ? Xb + (size_t)b*NN*GHD + c0 : (const float*)0;
    for (int i = tid; i < NN*16; i += 256) {
        int s = i >> 4, c = (i & 15)*4;
        float4 v = *(const float4*)&XaB[(size_t)s*GHD + c];
        if (XbB) {
            float4 w = *(const float4*)&XbB[(size_t)s*GHD + c];
            v.x += w.x; v.y += w.y; v.z += w.z; v.w += w.w;
        }
        *(float4*)&Hs[s*64 + c] = v;
    }
    if (tid < 64) bias_s[tid] = bias[c0 + tid];
    __syncthreads();

    unsigned long long acc[4][4];
    #pragma unroll
    for (int i = 0; i < 4; i++)
        #pragma unroll
        for (int j = 0; j < 4; j++) acc[i][j] = 0ull;

    #pragma unroll 4
    for (int s = 0; s < NN; s++) {
        float4 av = *(const float4*)&At[s*NN + ty*4];
        ulonglong2 h0 = *(const ulonglong2*)&Hs[s*64 + tx*8];
        ulonglong2 h1 = *(const ulonglong2*)&Hs[s*64 + tx*8 + 4];
        unsigned long long d0 = dup2(av.x), d1 = dup2(av.y);
        unsigned long long d2 = dup2(av.z), d3 = dup2(av.w);
        ffma2(acc[0][0], d0, h0.x); ffma2(acc[0][1], d0, h0.y);
        ffma2(acc[0][2], d0, h1.x); ffma2(acc[0][3], d0, h1.y);
        ffma2(acc[1][0], d1, h0.x); ffma2(acc[1][1], d1, h0.y);
        ffma2(acc[1][2], d1, h1.x); ffma2(acc[1][3], d1, h1.y);
        ffma2(acc[2][0], d2, h0.x); ffma2(acc[2][1], d2, h0.y);
        ffma2(acc[2][2], d2, h1.x); ffma2(acc[2][3], d2, h1.y);
        ffma2(acc[3][0], d3, h0.x); ffma2(acc[3][1], d3, h0.y);
        ffma2(acc[3][2], d3, h1.x); ffma2(acc[3][3], d3, h1.y);
    }

    float bb[8];
    #pragma unroll
    for (int j = 0; j < 8; j++) bb[j] = bias_s[tx*8 + j];
    float ps[8];
    #pragma unroll
    for (int j = 0; j < 8; j++) ps[j] = 0.f;
    #pragma unroll
    for (int i = 0; i < 4; i++) {
        float v[8];
        #pragma unroll
        for (int p = 0; p < 4; p++) {
            float2 pr = *(float2*)&acc[i][p];
            v[2*p]   = fmaxf(pr.x + bb[2*p],   0.f);
            v[2*p+1] = fmaxf(pr.y + bb[2*p+1], 0.f);
        }
        if (!POOL) {
            // tf32 pre-round: h1 feeds tf32 MMA GEMM2
            int d = ty*4 + i;
            float* orow = outp + (size_t)b*NN*GHD + (size_t)d*GHD + c0 + tx*8;
            *(float4*)orow       = make_float4(tf32r(v[0]), tf32r(v[1]),
                                               tf32r(v[2]), tf32r(v[3]));
            *(float4*)(orow + 4) = make_float4(tf32r(v[4]), tf32r(v[5]),
                                               tf32r(v[6]), tf32r(v[7]));
        } else {
            #pragma unroll
            for (int j = 0; j < 8; j++) ps[j] += v[j];
        }
    }
    if (POOL) {
        *(float4*)&red[ty*64 + tx*8]     = make_float4(ps[0], ps[1], ps[2], ps[3]);
        *(float4*)&red[ty*64 + tx*8 + 4] = make_float4(ps[4], ps[5], ps[6], ps[7]);
        __syncthreads();
        if (tid < 64) {
            float ssum = 0.f;
            #pragma unroll
            for (int g = 0; g < 32; g++) ssum += red[g*64 + tid];
            outp[b*GHD + c0 + tid] = ssum * (1.f/NN);
        }
    }
}

// ---------------- K8: final 2-layer MLP (multi-accumulator ILP) ----------------
__global__ void k_fc(const float* __restrict__ lh, const float* __restrict__ Wf1,
                     const float* __restrict__ bf1, const float* __restrict__ Wf2,
                     const float* __restrict__ bf2, float* __restrict__ out) {
    __shared__ float in_s[HH + GHD]; // 896
    __shared__ float hs[FHD];        // 256
    int b = blockIdx.x, tid = threadIdx.x; // 256 threads
    for (int i = tid; i < HH; i += 256) in_s[i] = lh[(size_t)b*SS*HH + i];
    if (tid < GHD) in_s[HH + tid] = g_pool[b*GHD + tid];
    __syncthreads();
    float a0 = 0.f, a1 = 0.f, a2 = 0.f, a3 = 0.f;
    #pragma unroll 8
    for (int k = 0; k < HH + GHD; k += 4) {
        a0 += in_s[k+0]*Wf1[(size_t)(k+0)*FHD + tid];
        a1 += in_s[k+1]*Wf1[(size_t)(k+1)*FHD + tid];
        a2 += in_s[k+2]*Wf1[(size_t)(k+2)*FHD + tid];
        a3 += in_s[k+3]*Wf1[(size_t)(k+3)*FHD + tid];
    }
    hs[tid] = fmaxf(bf1[tid] + (a0 + a1) + (a2 + a3), 0.f);
    __syncthreads();
    if (tid < LL) {
        float o = bf2[tid];
        for (int j = 0; j < FHD; j++) o += hs[j]*Wf2[j*LL + tid];
        out[b*LL + tid] = o;
    }
}

// ---------------- launch ----------------
extern "C" void kernel_launch(void* const* d_in, const int* in_sizes, int n_in,
                              void* d_out, int out_size) {
    const float* lh     = (const float*)d_in[0];
    const int*   submap = (const int*)d_in[1];
    const int*   ei     = (const int*)d_in[2];
    int wbase = (in_sizes[3] == 1) ? 3 : 2;  // num_nodes may be materialized
    const float* wr  = (const float*)d_in[wbase + 1];
    const float* br  = (const float*)d_in[wbase + 2];
    const float* W1  = (const float*)d_in[wbase + 3];
    const float* b1  = (const float*)d_in[wbase + 4];
    const float* W2  = (const float*)d_in[wbase + 5];
    const float* b2  = (const float*)d_in[wbase + 6];
    const float* Wf1 = (const float*)d_in[wbase + 7];
    const float* bf1 = (const float*)d_in[wbase + 8];
    const float* Wf2 = (const float*)d_in[wbase + 9];
    const float* bf2 = (const float*)d_in[wbase + 10];
    float* out = (float*)d_out;

    float *p_nf, *p_wr1, *p_wr2, *p_x1, *p_h1, *p_x2, *p_pool;
    cudaGetSymbolAddress((void**)&p_nf,   g_nf);
    cudaGetSymbolAddress((void**)&p_wr1,  g_wr1);
    cudaGetSymbolAddress((void**)&p_wr2,  g_wr2);
    cudaGetSymbolAddress((void**)&p_x1,   g_x1);
    cudaGetSymbolAddress((void**)&p_h1,   g_h1);
    cudaGetSymbolAddress((void**)&p_x2,   g_x2);
    cudaGetSymbolAddress((void**)&p_pool, g_pool);

    const int smem_seg = (NN*128 + STG*1024 + SS + NN)*sizeof(float)
                       + (SS + NN)*sizeof(int);                                     // ~95 KB
    const int smem_adj = (NN*NN + NN)*sizeof(float);                                // ~66 KB
    const int smem_ah  = (NN*NN + NN*64 + 32*64 + 64)*sizeof(float);                // ~104.5 KB
    cudaFuncSetAttribute(k_segsum,    cudaFuncAttributeMaxDynamicSharedMemorySize, smem_seg);
    cudaFuncSetAttribute(k_adj,       cudaFuncAttributeMaxDynamicSharedMemorySize, smem_adj);
    cudaFuncSetAttribute(k_ah<false>, cudaFuncAttributeMaxDynamicSharedMemorySize, smem_ah);
    cudaFuncSetAttribute(k_ah<true>,  cudaFuncAttributeMaxDynamicSharedMemorySize, smem_ah);

    k_gate<<<(BB*SS*32)/256, 256>>>(lh, wr, br);
    k_segsum<<<dim3(6, BB), 128, smem_seg>>>(lh, submap);
    k_adj<<<BB, 256, smem_adj>>>(ei);
    k_round<<<(HH*GHD + 255)/256, 256>>>(W1, W2, p_wr1, p_wr2);
    k_mma<<<BNN/64, 128>>>(p_nf, p_wr1, p_x1, HH);
    k_ah<false><<<BB*2, 256, smem_ah>>>(p_x1, (const float*)0, b1, p_h1);
    k_mma<<<BNN/64, 128>>>(p_h1, p_wr2, p_x2, GHD);
    k_ah<true><<<BB*2, 256, smem_ah>>>(p_x2, (const float*)0, b2, p_pool);
    k_fc<<<BB, 256>>>(lh, Wf1, bf1, Wf2, bf2, out);
}